// round 6
// baseline (speedup 1.0000x reference)
#include <cuda_runtime.h>
#include <cstdint>
#include <math.h>

// Problem constants
#define DMODEL 1024
#define HEADS  16
#define DH     64
#define SEQ    2048
#define BATCH  2
#define TROWS  (BATCH*SEQ)   // 4096

// Scratch (allocation-free rule: __device__ globals)
__device__ float g_Q[TROWS*DMODEL];
__device__ float g_K[TROWS*DMODEL];
__device__ float g_V[TROWS*DMODEL];
__device__ float g_AO[TROWS*DMODEL];

// ---------------------------------------------------------------------------
// Helpers
// ---------------------------------------------------------------------------
__device__ __forceinline__ uint32_t smem_u32(const void* p) {
    uint32_t a;
    asm("{ .reg .u64 t; cvta.to.shared.u64 t, %1; cvt.u32.u64 %0, t; }"
        : "=r"(a) : "l"(p));
    return a;
}
__device__ __forceinline__ uint32_t f2tf32(float f) {
    uint32_t r;
    asm("cvt.rna.tf32.f32 %0, %1;" : "=r"(r) : "f"(f));
    return r;
}
__device__ __forceinline__ void mma_tf32(float* d, const uint32_t* a,
                                         const uint32_t* b) {
    asm volatile(
        "mma.sync.aligned.m16n8k8.row.col.f32.tf32.tf32.f32 "
        "{%0,%1,%2,%3}, {%4,%5,%6,%7}, {%8,%9}, {%0,%1,%2,%3};"
        : "+f"(d[0]), "+f"(d[1]), "+f"(d[2]), "+f"(d[3])
        : "r"(a[0]), "r"(a[1]), "r"(a[2]), "r"(a[3]), "r"(b[0]), "r"(b[1]));
}
#define CP16(dst, src) \
    asm volatile("cp.async.cg.shared.global [%0], [%1], 16;" \
                 :: "r"(dst), "l"(src) : "memory")
#define CP_COMMIT() asm volatile("cp.async.commit_group;" ::: "memory")
#define CP_WAIT0()  asm volatile("cp.async.wait_group 0;"  ::: "memory")

// ---------------------------------------------------------------------------
// tf32 mma.sync GEMM: C[M,N] = A[M,K]*B[K,N], fp32 in/out.
// CTA 128x128, 8 warps, warp tile 64x32, K-chunk 32.
// R6: TRIPLE-buffered SMEM ring, ONE __syncthreads per chunk:
//   STS(c+1) [regs preloaded] -> LDG(c+2) -> MMA(c) -> sync.
// ---------------------------------------------------------------------------
#define GEMM_DSMEM 98304   // 3 x 16KB A + 3 x 16KB B

__global__ __launch_bounds__(256) void tgemm_kernel(
    const float* __restrict__ A, const float* __restrict__ B,
    float* __restrict__ C, int M, int N, int K)
{
    extern __shared__ __align__(16) char dyn[];
    const uint32_t base = smem_u32(dyn);
    // A buffers at base + bi*16384 (bi 0..2); B buffers at base + 49152 + bi*16384

    const int tid  = threadIdx.x;
    const int lane = tid & 31;
    const int wid  = tid >> 5;
    const int m0 = blockIdx.y * 128;
    const int n0 = blockIdx.x * 128;

    const int pr = lane >> 2;
    const int pc = lane & 3;
    const int MBa = wid;
    const int NBb = wid;

    const float* pA0 = A + (size_t)(m0 + MBa * 16 + pr) * K + pc;
    const float* pA1 = pA0 + (size_t)8 * K;

    float areg[16], breg[16];

    #define LDG_CHUNK(k0)                                                   \
    {                                                                       \
        _Pragma("unroll")                                                   \
        for (int q = 0; q < 4; q++) {                                       \
            int kq = (k0) + q * 8;                                          \
            areg[q * 4 + 0] = pA0[kq];                                      \
            areg[q * 4 + 1] = pA1[kq];                                      \
            areg[q * 4 + 2] = pA0[kq + 4];                                  \
            areg[q * 4 + 3] = pA1[kq + 4];                                  \
        }                                                                   \
        _Pragma("unroll")                                                   \
        for (int h = 0; h < 2; h++)                                         \
            _Pragma("unroll")                                               \
            for (int q = 0; q < 4; q++) {                                   \
                int k = (k0) + q * 8 + pc;                                  \
                int n = n0 + (NBb + 8 * h) * 8 + pr;                        \
                breg[(h * 4 + q) * 2 + 0] = B[(size_t)k * N + n];           \
                breg[(h * 4 + q) * 2 + 1] = B[(size_t)(k + 4) * N + n];     \
            }                                                               \
    }

    #define STS_CHUNK(bi)                                                   \
    {                                                                       \
        uint32_t ba = base + (uint32_t)(bi) * 16384u;                       \
        uint32_t bb = base + 49152u + (uint32_t)(bi) * 16384u;              \
        _Pragma("unroll")                                                   \
        for (int q = 0; q < 4; q++) {                                       \
            uint32_t off = ba + (uint32_t)(((q * 8 + MBa) * 128 + lane * 4) * 4); \
            uint32_t x = f2tf32(areg[q * 4 + 0]);                           \
            uint32_t y = f2tf32(areg[q * 4 + 1]);                           \
            uint32_t z = f2tf32(areg[q * 4 + 2]);                           \
            uint32_t w = f2tf32(areg[q * 4 + 3]);                           \
            asm volatile("st.shared.v4.b32 [%0], {%1,%2,%3,%4};"            \
                         :: "r"(off), "r"(x), "r"(y), "r"(z), "r"(w) : "memory"); \
        }                                                                   \
        _Pragma("unroll")                                                   \
        for (int h = 0; h < 2; h++)                                         \
            _Pragma("unroll")                                               \
            for (int q = 0; q < 4; q++) {                                   \
                uint32_t off = bb + (uint32_t)(((q * 16 + NBb + 8 * h) * 64 + lane * 2) * 4); \
                uint32_t x = f2tf32(breg[(h * 4 + q) * 2 + 0]);             \
                uint32_t y = f2tf32(breg[(h * 4 + q) * 2 + 1]);             \
                asm volatile("st.shared.v2.b32 [%0], {%1,%2};"              \
                             :: "r"(off), "r"(x), "r"(y) : "memory");       \
            }                                                               \
    }

    const int wmb = (wid & 1) * 4;
    const int wnb = (wid >> 1) * 4;

    float acc[4][4][4];
    #pragma unroll
    for (int i = 0; i < 4; i++)
        #pragma unroll
        for (int j = 0; j < 4; j++)
            #pragma unroll
            for (int r = 0; r < 4; r++) acc[i][j][r] = 0.f;

    #define MMA_CHUNK(bi)                                                   \
    {                                                                       \
        uint32_t ba = base + (uint32_t)(bi) * 16384u;                       \
        uint32_t bb = base + 49152u + (uint32_t)(bi) * 16384u;              \
        _Pragma("unroll")                                                   \
        for (int KS = 0; KS < 4; KS++) {                                    \
            uint32_t af[4][4], bf[4][2];                                    \
            _Pragma("unroll")                                               \
            for (int mb = 0; mb < 4; mb++) {                                \
                uint32_t off = ba + (uint32_t)(((KS * 8 + wmb + mb) * 128 + lane * 4) * 4); \
                asm volatile("ld.shared.v4.b32 {%0,%1,%2,%3}, [%4];"        \
                             : "=r"(af[mb][0]), "=r"(af[mb][1]),            \
                               "=r"(af[mb][2]), "=r"(af[mb][3])             \
                             : "r"(off));                                   \
            }                                                               \
            _Pragma("unroll")                                               \
            for (int nb = 0; nb < 4; nb++) {                                \
                uint32_t off = bb + (uint32_t)(((KS * 16 + wnb + nb) * 64 + lane * 2) * 4); \
                asm volatile("ld.shared.v2.b32 {%0,%1}, [%2];"              \
                             : "=r"(bf[nb][0]), "=r"(bf[nb][1]) : "r"(off));\
            }                                                               \
            _Pragma("unroll")                                               \
            for (int mb = 0; mb < 4; mb++)                                  \
                _Pragma("unroll")                                           \
                for (int nb = 0; nb < 4; nb++)                              \
                    mma_tf32(acc[mb][nb], af[mb], bf[nb]);                  \
        }                                                                   \
    }

    const int nch = K / 32;   // 32

    LDG_CHUNK(0);
    STS_CHUNK(0);
    LDG_CHUNK(32);
    __syncthreads();

    for (int c = 0; c < nch; c++) {
        if (c + 1 < nch) STS_CHUNK((c + 1) % 3);       // regs hold chunk c+1
        if (c + 2 < nch) LDG_CHUNK((c + 2) * 32);      // prefetch chunk c+2
        MMA_CHUNK(c % 3);
        __syncthreads();
    }

    #pragma unroll
    for (int mb = 0; mb < 4; mb++) {
        const int row = m0 + (wmb + mb) * 16 + (lane >> 2);
        #pragma unroll
        for (int nb = 0; nb < 4; nb++) {
            const int col = n0 + (wnb + nb) * 8 + 2 * (lane & 3);
            float2 v0 = make_float2(acc[mb][nb][0], acc[mb][nb][1]);
            float2 v1 = make_float2(acc[mb][nb][2], acc[mb][nb][3]);
            *(float2*)&C[(size_t)row * N + col]       = v0;
            *(float2*)&C[(size_t)(row + 8) * N + col] = v1;
        }
    }
    #undef LDG_CHUNK
    #undef STS_CHUNK
    #undef MMA_CHUNK
}

// ---------------------------------------------------------------------------
// RoPE applied in-place to g_Q and g_K.
// ---------------------------------------------------------------------------
__global__ void rope_kernel(const float* __restrict__ cosT,
                            const float* __restrict__ sinT)
{
    int idx = blockIdx.x * blockDim.x + threadIdx.x;   // over TROWS*HEADS*32
    if (idx >= TROWS * HEADS * 32) return;
    int d = idx & 31;
    int h = (idx >> 5) & (HEADS - 1);
    int t = idx >> 9;
    int s = t & (SEQ - 1);
    float c  = cosT[s * 32 + d];
    float sn = sinT[s * 32 + d];
    int base = t * DMODEL + h * DH;

    float q1 = g_Q[base + d], q2 = g_Q[base + d + 32];
    g_Q[base + d]      = q1 * c - q2 * sn;
    g_Q[base + d + 32] = q2 * c + q1 * sn;

    float k1 = g_K[base + d], k2 = g_K[base + d + 32];
    g_K[base + d]      = k1 * c - k2 * sn;
    g_K[base + d + 32] = k2 * c + k1 * sn;
}

// ---------------------------------------------------------------------------
// Tensor-core causal flash attention.
// CTA: 128 threads (4 warps), 64-query tile, 64-key tiles.
// S = Q K^T via 3xTF32; P*V via single tf32. Q persistent in registers.
// R6: K/V tiles arrive via cp.async.cg into double-buffered raw fp32 staging
// (pitch-68 rows -> conflict-free LDS); the copy for tile kt+1 is issued
// right after barrier (a) of tile kt, overlapping the entire tile's compute.
// SMEM (bytes): Khi 0, Klo 16K, Vrec 32K, P 48K+w*4352,
//               Kraw 66560+sb*17408, Vraw 101376+sb*17408.  Total 136192.
// ---------------------------------------------------------------------------
#define ATT_DSMEM 136192

__global__ __launch_bounds__(128) void attn_kernel()
{
    extern __shared__ __align__(16) char dynA[];
    const uint32_t Khi = smem_u32(dynA);
    const uint32_t Klo = Khi + 16384u;
    const uint32_t Vsm = Khi + 32768u;
    const uint32_t Pal = Khi + 49152u;
    const uint32_t Kst = Khi + 66560u;    // + sb*17408
    const uint32_t Vst = Khi + 101376u;   // + sb*17408

    const int tid  = threadIdx.x;
    const int lane = tid & 31;
    const int w    = tid >> 5;
    const uint32_t Pb = Pal + (uint32_t)w * 4352u;
    const int gid = lane >> 2;
    const int tg  = lane & 3;

    const int qt = (SEQ / 64 - 1) - blockIdx.x;   // heavy tiles first
    const int h  = blockIdx.y;
    const int b  = blockIdx.z;
    const int qbase = b * SEQ + qt * 64;

    // staging copy geometry: thread -> (key row, 128B half-row)
    const int skey  = tid >> 1;
    const int shalf = tid & 1;

    #define STAGE_TILE(kt_, sb_)                                              \
    {                                                                         \
        const int kb_ = b * SEQ + (kt_) * 64;                                 \
        const float* ks = g_K + (size_t)(kb_ + skey) * DMODEL + h * DH + shalf * 32; \
        const float* vs = g_V + (size_t)(kb_ + skey) * DMODEL + h * DH + shalf * 32; \
        uint32_t kd = Kst + (uint32_t)(sb_) * 17408u                          \
                          + (uint32_t)((skey * 68 + shalf * 32) * 4);         \
        uint32_t vd = Vst + (uint32_t)(sb_) * 17408u                          \
                          + (uint32_t)((skey * 68 + shalf * 32) * 4);         \
        _Pragma("unroll")                                                     \
        for (int c_ = 0; c_ < 8; c_++) {                                      \
            CP16(kd + c_ * 16, ks + c_ * 4);                                  \
            CP16(vd + c_ * 16, vs + c_ * 4);                                  \
        }                                                                     \
        CP_COMMIT();                                                          \
    }

    // ---- persistent Q fragments (hi/lo split) ----
    uint32_t qhi[8][4], qlo[8][4];
    {
        const float* qp = g_Q + (size_t)(qbase + w * 16) * DMODEL + h * DH;
        #pragma unroll
        for (int kb = 0; kb < 8; kb++) {
            float v[4];
            v[0] = qp[(size_t)gid       * DMODEL + kb * 8 + tg];
            v[1] = qp[(size_t)(gid + 8) * DMODEL + kb * 8 + tg];
            v[2] = qp[(size_t)gid       * DMODEL + kb * 8 + tg + 4];
            v[3] = qp[(size_t)(gid + 8) * DMODEL + kb * 8 + tg + 4];
            #pragma unroll
            for (int i = 0; i < 4; i++) {
                qhi[kb][i] = f2tf32(v[i]);
                qlo[kb][i] = f2tf32(v[i] - __uint_as_float(qhi[kb][i]));
            }
        }
    }

    STAGE_TILE(0, 0);   // prologue: stage tile 0

    float o[8][4];
    #pragma unroll
    for (int nb = 0; nb < 8; nb++)
        #pragma unroll
        for (int c = 0; c < 4; c++) o[nb][c] = 0.f;
    float mst[2] = {-1e30f, -1e30f};
    float lst[2] = {0.f, 0.f};

    for (int kt = 0; kt <= qt; kt++) {
        const int sb = kt & 1;
        CP_WAIT0();        // tile kt staged (this thread's chunks)
        __syncthreads();   // (a) prev tile consumers done + staging visible

        if (kt + 1 <= qt) STAGE_TILE(kt + 1, sb ^ 1);  // overlaps rest of tile

        const uint32_t Kr = Kst + (uint32_t)sb * 17408u;
        const uint32_t Vr = Vst + (uint32_t)sb * 17408u;

        // ---- produce fragment records from staging ----
        #pragma unroll
        for (int nn = 0; nn < 2; nn++) {
            const int nb = w + nn * 4;
            #pragma unroll
            for (int kb = 0; kb < 8; kb++) {
                const uint32_t off = (uint32_t)((((kb * 8 + nb) * 64) + lane * 2) * 4);
                float k0, k1;
                uint32_t kro = Kr + (uint32_t)(((nb * 8 + gid) * 68 + kb * 8 + tg) * 4);
                asm volatile("ld.shared.f32 %0, [%1];" : "=f"(k0) : "r"(kro));
                asm volatile("ld.shared.f32 %0, [%1];" : "=f"(k1) : "r"(kro + 16));
                uint32_t h0 = f2tf32(k0), h1 = f2tf32(k1);
                uint32_t l0 = f2tf32(k0 - __uint_as_float(h0));
                uint32_t l1 = f2tf32(k1 - __uint_as_float(h1));
                asm volatile("st.shared.v2.b32 [%0], {%1,%2};"
                             :: "r"(Khi + off), "r"(h0), "r"(h1) : "memory");
                asm volatile("st.shared.v2.b32 [%0], {%1,%2};"
                             :: "r"(Klo + off), "r"(l0), "r"(l1) : "memory");
                float v0f, v1f;
                uint32_t vro = Vr + (uint32_t)(((kb * 8 + tg) * 68 + nb * 8 + gid) * 4);
                asm volatile("ld.shared.f32 %0, [%1];" : "=f"(v0f) : "r"(vro));
                asm volatile("ld.shared.f32 %0, [%1];" : "=f"(v1f) : "r"(vro + 4 * 68 * 4));
                uint32_t v0 = f2tf32(v0f), v1 = f2tf32(v1f);
                asm volatile("st.shared.v2.b32 [%0], {%1,%2};"
                             :: "r"(Vsm + off), "r"(v0), "r"(v1) : "memory");
            }
        }
        __syncthreads();   // (b) records visible

        // ---- S = Q K^T (3xTF32) ----
        float s[8][4];
        #pragma unroll
        for (int nb = 0; nb < 8; nb++) {
            s[nb][0] = s[nb][1] = s[nb][2] = s[nb][3] = 0.f;
            #pragma unroll
            for (int kb = 0; kb < 8; kb++) {
                const uint32_t off = (uint32_t)((((kb * 8 + nb) * 64) + lane * 2) * 4);
                uint32_t kh[2], kl[2];
                asm volatile("ld.shared.v2.b32 {%0,%1}, [%2];"
                             : "=r"(kh[0]), "=r"(kh[1]) : "r"(Khi + off));
                asm volatile("ld.shared.v2.b32 {%0,%1}, [%2];"
                             : "=r"(kl[0]), "=r"(kl[1]) : "r"(Klo + off));
                mma_tf32(s[nb], qhi[kb], kh);
                mma_tf32(s[nb], qlo[kb], kh);
                mma_tf32(s[nb], qhi[kb], kl);
            }
        }

        // ---- scale + causal mask ----
        const bool diag = (kt == qt);
        #pragma unroll
        for (int nb = 0; nb < 8; nb++)
            #pragma unroll
            for (int c = 0; c < 4; c++) {
                s[nb][c] *= 0.125f;
                if (diag) {
                    int rl = w * 16 + gid + (c >> 1) * 8;
                    int cl = nb * 8 + 2 * tg + (c & 1);
                    if (cl > rl) s[nb][c] = -1e30f;
                }
            }

        // ---- online softmax ----
        #pragma unroll
        for (int rh = 0; rh < 2; rh++) {
            float mx = -1e30f;
            #pragma unroll
            for (int nb = 0; nb < 8; nb++)
                mx = fmaxf(mx, fmaxf(s[nb][rh * 2], s[nb][rh * 2 + 1]));
            mx = fmaxf(mx, __shfl_xor_sync(0xffffffffu, mx, 1));
            mx = fmaxf(mx, __shfl_xor_sync(0xffffffffu, mx, 2));
            float mnew  = fmaxf(mst[rh], mx);
            float alpha = __expf(mst[rh] - mnew);
            mst[rh] = mnew;
            float sum = 0.f;
            #pragma unroll
            for (int nb = 0; nb < 8; nb++) {
                float e0 = __expf(s[nb][rh * 2]     - mnew);
                float e1 = __expf(s[nb][rh * 2 + 1] - mnew);
                s[nb][rh * 2] = e0; s[nb][rh * 2 + 1] = e1;
                sum += e0 + e1;
            }
            sum += __shfl_xor_sync(0xffffffffu, sum, 1);
            sum += __shfl_xor_sync(0xffffffffu, sum, 2);
            lst[rh] = lst[rh] * alpha + sum;
            #pragma unroll
            for (int nb = 0; nb < 8; nb++) {
                o[nb][rh * 2]     *= alpha;
                o[nb][rh * 2 + 1] *= alpha;
            }
        }

        // ---- write P to padded per-warp SMEM ----
        #pragma unroll
        for (int nb = 0; nb < 8; nb++) {
            uint32_t p0 = f2tf32(s[nb][0]), p1 = f2tf32(s[nb][1]);
            uint32_t p2 = f2tf32(s[nb][2]), p3 = f2tf32(s[nb][3]);
            uint32_t o0 = Pb + (uint32_t)(((gid)     * 68 + nb * 8 + 2 * tg) * 4);
            uint32_t o1 = Pb + (uint32_t)(((gid + 8) * 68 + nb * 8 + 2 * tg) * 4);
            asm volatile("st.shared.v2.b32 [%0], {%1,%2};"
                         :: "r"(o0), "r"(p0), "r"(p1) : "memory");
            asm volatile("st.shared.v2.b32 [%0], {%1,%2};"
                         :: "r"(o1), "r"(p2), "r"(p3) : "memory");
        }
        __syncwarp();

        // ---- O += P * V ----
        #pragma unroll
        for (int kb = 0; kb < 8; kb++) {
            uint32_t a[4];
            asm volatile("ld.shared.b32 %0, [%1];" : "=r"(a[0])
                         : "r"(Pb + (uint32_t)(((gid)     * 68 + kb * 8 + tg)     * 4)));
            asm volatile("ld.shared.b32 %0, [%1];" : "=r"(a[1])
                         : "r"(Pb + (uint32_t)(((gid + 8) * 68 + kb * 8 + tg)     * 4)));
            asm volatile("ld.shared.b32 %0, [%1];" : "=r"(a[2])
                         : "r"(Pb + (uint32_t)(((gid)     * 68 + kb * 8 + tg + 4) * 4)));
            asm volatile("ld.shared.b32 %0, [%1];" : "=r"(a[3])
                         : "r"(Pb + (uint32_t)(((gid + 8) * 68 + kb * 8 + tg + 4) * 4)));
            #pragma unroll
            for (int nb = 0; nb < 8; nb++) {
                const uint32_t off = (uint32_t)((((kb * 8 + nb) * 64) + lane * 2) * 4);
                uint32_t bf[2];
                asm volatile("ld.shared.v2.b32 {%0,%1}, [%2];"
                             : "=r"(bf[0]), "=r"(bf[1]) : "r"(Vsm + off));
                mma_tf32(o[nb], a, bf);
            }
        }
        __syncwarp();
    }
    #undef STAGE_TILE

    // ---- epilogue: normalize, write g_AO ----
    #pragma unroll
    for (int rh = 0; rh < 2; rh++) {
        float inv = 1.f / lst[rh];
        int row = qbase + w * 16 + gid + rh * 8;
        float* dst = g_AO + (size_t)row * DMODEL + h * DH;
        #pragma unroll
        for (int nb = 0; nb < 8; nb++)
            *(float2*)(dst + nb * 8 + 2 * tg) =
                make_float2(o[nb][rh * 2] * inv, o[nb][rh * 2 + 1] * inv);
    }
}

// ---------------------------------------------------------------------------
// kernel_launch
// ---------------------------------------------------------------------------
extern "C" void kernel_launch(void* const* d_in, const int* in_sizes, int n_in,
                              void* d_out, int out_size)
{
    const float* X    = (const float*)d_in[0];
    const float* cosT = (const float*)d_in[1];
    const float* sinT = (const float*)d_in[2];
    const float* Wq   = (const float*)d_in[4];
    const float* Wk   = (const float*)d_in[5];
    const float* Wv   = (const float*)d_in[6];
    const float* Wo   = (const float*)d_in[7];
    float* out = (float*)d_out;

    float *pQ, *pK, *pV, *pAO;
    cudaGetSymbolAddress((void**)&pQ,  g_Q);
    cudaGetSymbolAddress((void**)&pK,  g_K);
    cudaGetSymbolAddress((void**)&pV,  g_V);
    cudaGetSymbolAddress((void**)&pAO, g_AO);

    cudaFuncSetAttribute(tgemm_kernel,
                         cudaFuncAttributeMaxDynamicSharedMemorySize, GEMM_DSMEM);
    cudaFuncSetAttribute(attn_kernel,
                         cudaFuncAttributeMaxDynamicSharedMemorySize, ATT_DSMEM);

    dim3 gemm_grid(DMODEL / 128, TROWS / 128);   // (8, 32)
    tgemm_kernel<<<gemm_grid, 256, GEMM_DSMEM>>>(X, Wq, pQ, TROWS, DMODEL, DMODEL);
    tgemm_kernel<<<gemm_grid, 256, GEMM_DSMEM>>>(X, Wk, pK, TROWS, DMODEL, DMODEL);
    tgemm_kernel<<<gemm_grid, 256, GEMM_DSMEM>>>(X, Wv, pV, TROWS, DMODEL, DMODEL);

    int rope_total = TROWS * HEADS * 32;
    rope_kernel<<<(rope_total + 255) / 256, 256>>>(cosT, sinT);

    dim3 attn_grid(SEQ / 64, HEADS, BATCH);      // (32, 16, 2)
    attn_kernel<<<attn_grid, 128, ATT_DSMEM>>>();

    tgemm_kernel<<<gemm_grid, 256, GEMM_DSMEM>>>(pAO, Wo, out, TROWS, DMODEL, DMODEL);

    (void)in_sizes; (void)n_in; (void)out_size;
}

// round 9
// speedup vs baseline: 1.1935x; 1.1935x over previous
#include <cuda_runtime.h>
#include <cstdint>
#include <math.h>

// Problem constants
#define DMODEL 1024
#define HEADS  16
#define DH     64
#define SEQ    2048
#define BATCH  2
#define TROWS  (BATCH*SEQ)   // 4096

// Scratch (allocation-free rule: __device__ globals)
__device__ float g_Q[TROWS*DMODEL];
__device__ float g_K[TROWS*DMODEL];
__device__ float g_V[TROWS*DMODEL];
__device__ float g_AO[TROWS*DMODEL];

// ---------------------------------------------------------------------------
// Helpers
// ---------------------------------------------------------------------------
__device__ __forceinline__ uint32_t smem_u32(const void* p) {
    uint32_t a;
    asm("{ .reg .u64 t; cvta.to.shared.u64 t, %1; cvt.u32.u64 %0, t; }"
        : "=r"(a) : "l"(p));
    return a;
}
__device__ __forceinline__ uint32_t f2tf32(float f) {
    uint32_t r;
    asm("cvt.rna.tf32.f32 %0, %1;" : "=r"(r) : "f"(f));
    return r;
}
__device__ __forceinline__ void mma_tf32(float* d, const uint32_t* a,
                                         const uint32_t* b) {
    asm volatile(
        "mma.sync.aligned.m16n8k8.row.col.f32.tf32.tf32.f32 "
        "{%0,%1,%2,%3}, {%4,%5,%6,%7}, {%8,%9}, {%0,%1,%2,%3};"
        : "+f"(d[0]), "+f"(d[1]), "+f"(d[2]), "+f"(d[3])
        : "r"(a[0]), "r"(a[1]), "r"(a[2]), "r"(a[3]), "r"(b[0]), "r"(b[1]));
}

// ---------------------------------------------------------------------------
// tf32 mma.sync GEMM: C[M,N] = A[M,K]*B[K,N], fp32 in/out.  (R6 version)
// CTA 128x128, 8 warps, warp tile 64x32, K-chunk 32.
// TRIPLE-buffered SMEM ring, ONE __syncthreads per chunk:
//   STS(c+1) [regs preloaded] -> LDG(c+2) -> MMA(c) -> sync.
// ---------------------------------------------------------------------------
#define GEMM_DSMEM 98304   // 3 x 16KB A + 3 x 16KB B

__global__ __launch_bounds__(256) void tgemm_kernel(
    const float* __restrict__ A, const float* __restrict__ B,
    float* __restrict__ C, int M, int N, int K)
{
    extern __shared__ __align__(16) char dyn[];
    const uint32_t base = smem_u32(dyn);

    const int tid  = threadIdx.x;
    const int lane = tid & 31;
    const int wid  = tid >> 5;
    const int m0 = blockIdx.y * 128;
    const int n0 = blockIdx.x * 128;

    const int pr = lane >> 2;
    const int pc = lane & 3;
    const int MBa = wid;
    const int NBb = wid;

    const float* pA0 = A + (size_t)(m0 + MBa * 16 + pr) * K + pc;
    const float* pA1 = pA0 + (size_t)8 * K;

    float areg[16], breg[16];

    #define LDG_CHUNK(k0)                                                   \
    {                                                                       \
        _Pragma("unroll")                                                   \
        for (int q = 0; q < 4; q++) {                                       \
            int kq = (k0) + q * 8;                                          \
            areg[q * 4 + 0] = pA0[kq];                                      \
            areg[q * 4 + 1] = pA1[kq];                                      \
            areg[q * 4 + 2] = pA0[kq + 4];                                  \
            areg[q * 4 + 3] = pA1[kq + 4];                                  \
        }                                                                   \
        _Pragma("unroll")                                                   \
        for (int h = 0; h < 2; h++)                                         \
            _Pragma("unroll")                                               \
            for (int q = 0; q < 4; q++) {                                   \
                int k = (k0) + q * 8 + pc;                                  \
                int n = n0 + (NBb + 8 * h) * 8 + pr;                        \
                breg[(h * 4 + q) * 2 + 0] = B[(size_t)k * N + n];           \
                breg[(h * 4 + q) * 2 + 1] = B[(size_t)(k + 4) * N + n];     \
            }                                                               \
    }

    #define STS_CHUNK(bi)                                                   \
    {                                                                       \
        uint32_t ba = base + (uint32_t)(bi) * 16384u;                       \
        uint32_t bb = base + 49152u + (uint32_t)(bi) * 16384u;              \
        _Pragma("unroll")                                                   \
        for (int q = 0; q < 4; q++) {                                       \
            uint32_t off = ba + (uint32_t)(((q * 8 + MBa) * 128 + lane * 4) * 4); \
            uint32_t x = f2tf32(areg[q * 4 + 0]);                           \
            uint32_t y = f2tf32(areg[q * 4 + 1]);                           \
            uint32_t z = f2tf32(areg[q * 4 + 2]);                           \
            uint32_t w = f2tf32(areg[q * 4 + 3]);                           \
            asm volatile("st.shared.v4.b32 [%0], {%1,%2,%3,%4};"            \
                         :: "r"(off), "r"(x), "r"(y), "r"(z), "r"(w) : "memory"); \
        }                                                                   \
        _Pragma("unroll")                                                   \
        for (int h = 0; h < 2; h++)                                         \
            _Pragma("unroll")                                               \
            for (int q = 0; q < 4; q++) {                                   \
                uint32_t off = bb + (uint32_t)(((q * 16 + NBb + 8 * h) * 64 + lane * 2) * 4); \
                uint32_t x = f2tf32(breg[(h * 4 + q) * 2 + 0]);             \
                uint32_t y = f2tf32(breg[(h * 4 + q) * 2 + 1]);             \
                asm volatile("st.shared.v2.b32 [%0], {%1,%2};"              \
                             :: "r"(off), "r"(x), "r"(y) : "memory");       \
            }                                                               \
    }

    const int wmb = (wid & 1) * 4;
    const int wnb = (wid >> 1) * 4;

    float acc[4][4][4];
    #pragma unroll
    for (int i = 0; i < 4; i++)
        #pragma unroll
        for (int j = 0; j < 4; j++)
            #pragma unroll
            for (int r = 0; r < 4; r++) acc[i][j][r] = 0.f;

    #define MMA_CHUNK(bi)                                                   \
    {                                                                       \
        uint32_t ba = base + (uint32_t)(bi) * 16384u;                       \
        uint32_t bb = base + 49152u + (uint32_t)(bi) * 16384u;              \
        _Pragma("unroll")                                                   \
        for (int KS = 0; KS < 4; KS++) {                                    \
            uint32_t af[4][4], bf[4][2];                                    \
            _Pragma("unroll")                                               \
            for (int mb = 0; mb < 4; mb++) {                                \
                uint32_t off = ba + (uint32_t)(((KS * 8 + wmb + mb) * 128 + lane * 4) * 4); \
                asm volatile("ld.shared.v4.b32 {%0,%1,%2,%3}, [%4];"        \
                             : "=r"(af[mb][0]), "=r"(af[mb][1]),            \
                               "=r"(af[mb][2]), "=r"(af[mb][3])             \
                             : "r"(off));                                   \
            }                                                               \
            _Pragma("unroll")                                               \
            for (int nb = 0; nb < 4; nb++) {                                \
                uint32_t off = bb + (uint32_t)(((KS * 16 + wnb + nb) * 64 + lane * 2) * 4); \
                asm volatile("ld.shared.v2.b32 {%0,%1}, [%2];"              \
                             : "=r"(bf[nb][0]), "=r"(bf[nb][1]) : "r"(off));\
            }                                                               \
            _Pragma("unroll")                                               \
            for (int mb = 0; mb < 4; mb++)                                  \
                _Pragma("unroll")                                           \
                for (int nb = 0; nb < 4; nb++)                              \
                    mma_tf32(acc[mb][nb], af[mb], bf[nb]);                  \
        }                                                                   \
    }

    const int nch = K / 32;   // 32

    LDG_CHUNK(0);
    STS_CHUNK(0);
    LDG_CHUNK(32);
    __syncthreads();

    for (int c = 0; c < nch; c++) {
        if (c + 1 < nch) STS_CHUNK((c + 1) % 3);       // regs hold chunk c+1
        if (c + 2 < nch) LDG_CHUNK((c + 2) * 32);      // prefetch chunk c+2
        MMA_CHUNK(c % 3);
        __syncthreads();
    }

    #pragma unroll
    for (int mb = 0; mb < 4; mb++) {
        const int row = m0 + (wmb + mb) * 16 + (lane >> 2);
        #pragma unroll
        for (int nb = 0; nb < 4; nb++) {
            const int col = n0 + (wnb + nb) * 8 + 2 * (lane & 3);
            float2 v0 = make_float2(acc[mb][nb][0], acc[mb][nb][1]);
            float2 v1 = make_float2(acc[mb][nb][2], acc[mb][nb][3]);
            *(float2*)&C[(size_t)row * N + col]       = v0;
            *(float2*)&C[(size_t)(row + 8) * N + col] = v1;
        }
    }
    #undef LDG_CHUNK
    #undef STS_CHUNK
    #undef MMA_CHUNK
}

// ---------------------------------------------------------------------------
// RoPE applied in-place to g_Q and g_K.
// ---------------------------------------------------------------------------
__global__ void rope_kernel(const float* __restrict__ cosT,
                            const float* __restrict__ sinT)
{
    int idx = blockIdx.x * blockDim.x + threadIdx.x;   // over TROWS*HEADS*32
    if (idx >= TROWS * HEADS * 32) return;
    int d = idx & 31;
    int h = (idx >> 5) & (HEADS - 1);
    int t = idx >> 9;
    int s = t & (SEQ - 1);
    float c  = cosT[s * 32 + d];
    float sn = sinT[s * 32 + d];
    int base = t * DMODEL + h * DH;

    float q1 = g_Q[base + d], q2 = g_Q[base + d + 32];
    g_Q[base + d]      = q1 * c - q2 * sn;
    g_Q[base + d + 32] = q2 * c + q1 * sn;

    float k1 = g_K[base + d], k2 = g_K[base + d + 32];
    g_K[base + d]      = k1 * c - k2 * sn;
    g_K[base + d + 32] = k2 * c + k1 * sn;
}

// ---------------------------------------------------------------------------
// Tensor-core causal flash attention.  (R5 version — 65KB smem, 3 CTAs/SM)
// CTA: 128 threads (4 warps), 64-query tile; warp w owns rows [w*16, w*16+16).
// Key tiles of 64. S = Q*K^T via 3xTF32 (hi/lo split); P*V single tf32.
// Q persistent register fragments; K(hi/lo), V staged in SMEM as mma
// B-fragment records; P via padded per-warp SMEM (pitch 68, conflict-free).
// SMEM map (bytes): Khi 0..16K, Klo 16K..32K, V 32K..48K, P 48K + w*4352.
// ---------------------------------------------------------------------------
#define ATT_DSMEM (49152 + 4*4352)   // 66560

__global__ __launch_bounds__(128) void attn_kernel()
{
    extern __shared__ __align__(16) char dynA[];
    const uint32_t Khi = smem_u32(dynA);
    const uint32_t Klo = Khi + 16384u;
    const uint32_t Vsm = Khi + 32768u;

    const int tid  = threadIdx.x;
    const int lane = tid & 31;
    const int w    = tid >> 5;
    const uint32_t Pb = Khi + 49152u + (uint32_t)w * 4352u;
    const int gid = lane >> 2;    // group id (row within 8-block)
    const int tg  = lane & 3;     // thread in group

    const int qt = (SEQ / 64 - 1) - blockIdx.x;   // heavy tiles first
    const int h  = blockIdx.y;
    const int b  = blockIdx.z;
    const int qbase = b * SEQ + qt * 64;

    // ---- persistent Q fragments (hi/lo split) ----
    uint32_t qhi[8][4], qlo[8][4];
    {
        const float* qp = g_Q + (size_t)(qbase + w * 16) * DMODEL + h * DH;
        #pragma unroll
        for (int kb = 0; kb < 8; kb++) {
            float v[4];
            v[0] = qp[(size_t)gid       * DMODEL + kb * 8 + tg];
            v[1] = qp[(size_t)(gid + 8) * DMODEL + kb * 8 + tg];
            v[2] = qp[(size_t)gid       * DMODEL + kb * 8 + tg + 4];
            v[3] = qp[(size_t)(gid + 8) * DMODEL + kb * 8 + tg + 4];
            #pragma unroll
            for (int i = 0; i < 4; i++) {
                qhi[kb][i] = f2tf32(v[i]);
                qlo[kb][i] = f2tf32(v[i] - __uint_as_float(qhi[kb][i]));
            }
        }
    }

    float o[8][4];
    #pragma unroll
    for (int nb = 0; nb < 8; nb++)
        #pragma unroll
        for (int c = 0; c < 4; c++) o[nb][c] = 0.f;
    float mst[2] = {-1e30f, -1e30f};
    float lst[2] = {0.f, 0.f};

    for (int kt = 0; kt <= qt; kt++) {
        const int kbase = b * SEQ + kt * 64;
        __syncthreads();   // previous tile's consumers done

        // ---- producers: warp w fills records nb = w and w+4 ----
        #pragma unroll
        for (int nn = 0; nn < 2; nn++) {
            const int nb = w + nn * 4;
            #pragma unroll
            for (int kb = 0; kb < 8; kb++) {
                const uint32_t off = (uint32_t)((((kb * 8 + nb) * 64) + lane * 2) * 4);
                const float* kp = g_K + (size_t)(kbase + nb * 8 + gid) * DMODEL
                                      + h * DH + kb * 8 + tg;
                float k0 = kp[0], k1 = kp[4];
                uint32_t h0 = f2tf32(k0), h1 = f2tf32(k1);
                uint32_t l0 = f2tf32(k0 - __uint_as_float(h0));
                uint32_t l1 = f2tf32(k1 - __uint_as_float(h1));
                asm volatile("st.shared.v2.b32 [%0], {%1,%2};"
                             :: "r"(Khi + off), "r"(h0), "r"(h1) : "memory");
                asm volatile("st.shared.v2.b32 [%0], {%1,%2};"
                             :: "r"(Klo + off), "r"(l0), "r"(l1) : "memory");
                const float* vp = g_V + (size_t)(kbase + kb * 8 + tg) * DMODEL
                                      + h * DH + nb * 8 + gid;
                uint32_t v0 = f2tf32(vp[0]);
                uint32_t v1 = f2tf32(vp[(size_t)4 * DMODEL]);
                asm volatile("st.shared.v2.b32 [%0], {%1,%2};"
                             :: "r"(Vsm + off), "r"(v0), "r"(v1) : "memory");
            }
        }
        __syncthreads();

        // ---- S = Q K^T (3xTF32) ----
        float s[8][4];
        #pragma unroll
        for (int nb = 0; nb < 8; nb++) {
            s[nb][0] = s[nb][1] = s[nb][2] = s[nb][3] = 0.f;
            #pragma unroll
            for (int kb = 0; kb < 8; kb++) {
                const uint32_t off = (uint32_t)((((kb * 8 + nb) * 64) + lane * 2) * 4);
                uint32_t kh[2], kl[2];
                asm volatile("ld.shared.v2.b32 {%0,%1}, [%2];"
                             : "=r"(kh[0]), "=r"(kh[1]) : "r"(Khi + off));
                asm volatile("ld.shared.v2.b32 {%0,%1}, [%2];"
                             : "=r"(kl[0]), "=r"(kl[1]) : "r"(Klo + off));
                mma_tf32(s[nb], qhi[kb], kh);
                mma_tf32(s[nb], qlo[kb], kh);
                mma_tf32(s[nb], qhi[kb], kl);
            }
        }

        // ---- scale + causal mask (diagonal tile only) ----
        const bool diag = (kt == qt);
        #pragma unroll
        for (int nb = 0; nb < 8; nb++)
            #pragma unroll
            for (int c = 0; c < 4; c++) {
                s[nb][c] *= 0.125f;
                if (diag) {
                    int rl = w * 16 + gid + (c >> 1) * 8;
                    int cl = nb * 8 + 2 * tg + (c & 1);
                    if (cl > rl) s[nb][c] = -1e30f;
                }
            }

        // ---- online softmax (rows gid and gid+8; reduce across quad lanes) ----
        #pragma unroll
        for (int rh = 0; rh < 2; rh++) {
            float mx = -1e30f;
            #pragma unroll
            for (int nb = 0; nb < 8; nb++)
                mx = fmaxf(mx, fmaxf(s[nb][rh * 2], s[nb][rh * 2 + 1]));
            mx = fmaxf(mx, __shfl_xor_sync(0xffffffffu, mx, 1));
            mx = fmaxf(mx, __shfl_xor_sync(0xffffffffu, mx, 2));
            float mnew  = fmaxf(mst[rh], mx);
            float alpha = __expf(mst[rh] - mnew);
            mst[rh] = mnew;
            float sum = 0.f;
            #pragma unroll
            for (int nb = 0; nb < 8; nb++) {
                float e0 = __expf(s[nb][rh * 2]     - mnew);
                float e1 = __expf(s[nb][rh * 2 + 1] - mnew);
                s[nb][rh * 2] = e0; s[nb][rh * 2 + 1] = e1;
                sum += e0 + e1;
            }
            sum += __shfl_xor_sync(0xffffffffu, sum, 1);
            sum += __shfl_xor_sync(0xffffffffu, sum, 2);
            lst[rh] = lst[rh] * alpha + sum;
            #pragma unroll
            for (int nb = 0; nb < 8; nb++) {
                o[nb][rh * 2]     *= alpha;
                o[nb][rh * 2 + 1] *= alpha;
            }
        }

        // ---- write P (tf32 bits) to padded per-warp SMEM ----
        #pragma unroll
        for (int nb = 0; nb < 8; nb++) {
            uint32_t p0 = f2tf32(s[nb][0]), p1 = f2tf32(s[nb][1]);
            uint32_t p2 = f2tf32(s[nb][2]), p3 = f2tf32(s[nb][3]);
            uint32_t o0 = Pb + (uint32_t)(((gid)     * 68 + nb * 8 + 2 * tg) * 4);
            uint32_t o1 = Pb + (uint32_t)(((gid + 8) * 68 + nb * 8 + 2 * tg) * 4);
            asm volatile("st.shared.v2.b32 [%0], {%1,%2};"
                         :: "r"(o0), "r"(p0), "r"(p1) : "memory");
            asm volatile("st.shared.v2.b32 [%0], {%1,%2};"
                         :: "r"(o1), "r"(p2), "r"(p3) : "memory");
        }
        __syncwarp();

        // ---- O += P * V ----
        #pragma unroll
        for (int kb = 0; kb < 8; kb++) {
            uint32_t a[4];
            asm volatile("ld.shared.b32 %0, [%1];" : "=r"(a[0])
                         : "r"(Pb + (uint32_t)(((gid)     * 68 + kb * 8 + tg)     * 4)));
            asm volatile("ld.shared.b32 %0, [%1];" : "=r"(a[1])
                         : "r"(Pb + (uint32_t)(((gid + 8) * 68 + kb * 8 + tg)     * 4)));
            asm volatile("ld.shared.b32 %0, [%1];" : "=r"(a[2])
                         : "r"(Pb + (uint32_t)(((gid)     * 68 + kb * 8 + tg + 4) * 4)));
            asm volatile("ld.shared.b32 %0, [%1];" : "=r"(a[3])
                         : "r"(Pb + (uint32_t)(((gid + 8) * 68 + kb * 8 + tg + 4) * 4)));
            #pragma unroll
            for (int nb = 0; nb < 8; nb++) {
                const uint32_t off = (uint32_t)((((kb * 8 + nb) * 64) + lane * 2) * 4);
                uint32_t bf[2];
                asm volatile("ld.shared.v2.b32 {%0,%1}, [%2];"
                             : "=r"(bf[0]), "=r"(bf[1]) : "r"(Vsm + off));
                mma_tf32(o[nb], a, bf);
            }
        }
        __syncwarp();
    }

    // ---- epilogue: normalize, write g_AO ----
    #pragma unroll
    for (int rh = 0; rh < 2; rh++) {
        float inv = 1.f / lst[rh];
        int row = qbase + w * 16 + gid + rh * 8;
        float* dst = g_AO + (size_t)row * DMODEL + h * DH;
        #pragma unroll
        for (int nb = 0; nb < 8; nb++)
            *(float2*)(dst + nb * 8 + 2 * tg) =
                make_float2(o[nb][rh * 2] * inv, o[nb][rh * 2 + 1] * inv);
    }
}

// ---------------------------------------------------------------------------
// kernel_launch
// ---------------------------------------------------------------------------
extern "C" void kernel_launch(void* const* d_in, const int* in_sizes, int n_in,
                              void* d_out, int out_size)
{
    const float* X    = (const float*)d_in[0];
    const float* cosT = (const float*)d_in[1];
    const float* sinT = (const float*)d_in[2];
    const float* Wq   = (const float*)d_in[4];
    const float* Wk   = (const float*)d_in[5];
    const float* Wv   = (const float*)d_in[6];
    const float* Wo   = (const float*)d_in[7];
    float* out = (float*)d_out;

    float *pQ, *pK, *pV, *pAO;
    cudaGetSymbolAddress((void**)&pQ,  g_Q);
    cudaGetSymbolAddress((void**)&pK,  g_K);
    cudaGetSymbolAddress((void**)&pV,  g_V);
    cudaGetSymbolAddress((void**)&pAO, g_AO);

    cudaFuncSetAttribute(tgemm_kernel,
                         cudaFuncAttributeMaxDynamicSharedMemorySize, GEMM_DSMEM);
    cudaFuncSetAttribute(attn_kernel,
                         cudaFuncAttributeMaxDynamicSharedMemorySize, ATT_DSMEM);

    dim3 gemm_grid(DMODEL / 128, TROWS / 128);   // (8, 32)
    tgemm_kernel<<<gemm_grid, 256, GEMM_DSMEM>>>(X, Wq, pQ, TROWS, DMODEL, DMODEL);
    tgemm_kernel<<<gemm_grid, 256, GEMM_DSMEM>>>(X, Wk, pK, TROWS, DMODEL, DMODEL);
    tgemm_kernel<<<gemm_grid, 256, GEMM_DSMEM>>>(X, Wv, pV, TROWS, DMODEL, DMODEL);

    int rope_total = TROWS * HEADS * 32;
    rope_kernel<<<(rope_total + 255) / 256, 256>>>(cosT, sinT);

    dim3 attn_grid(SEQ / 64, HEADS, BATCH);      // (32, 16, 2)
    attn_kernel<<<attn_grid, 128, ATT_DSMEM>>>();

    tgemm_kernel<<<gemm_grid, 256, GEMM_DSMEM>>>(pAO, Wo, out, TROWS, DMODEL, DMODEL);

    (void)in_sizes; (void)n_in; (void)out_size;
}

// round 11
// speedup vs baseline: 1.2977x; 1.0873x over previous
#include <cuda_runtime.h>
#include <cstdint>
#include <math.h>

// Problem constants
#define DMODEL 1024
#define HEADS  16
#define DH     64
#define SEQ    2048
#define BATCH  2
#define TROWS  (BATCH*SEQ)   // 4096

// Scratch (allocation-free rule: __device__ globals)
__device__ float g_Q[TROWS*DMODEL];
__device__ float g_K[TROWS*DMODEL];
__device__ float g_V[TROWS*DMODEL];
__device__ float g_AO[TROWS*DMODEL];

// ---------------------------------------------------------------------------
// Helpers
// ---------------------------------------------------------------------------
__device__ __forceinline__ uint32_t smem_u32(const void* p) {
    uint32_t a;
    asm("{ .reg .u64 t; cvta.to.shared.u64 t, %1; cvt.u32.u64 %0, t; }"
        : "=r"(a) : "l"(p));
    return a;
}
__device__ __forceinline__ uint32_t f2tf32(float f) {
    uint32_t r;
    asm("cvt.rna.tf32.f32 %0, %1;" : "=r"(r) : "f"(f));
    return r;
}
__device__ __forceinline__ void mma_tf32(float* d, const uint32_t* a,
                                         const uint32_t* b) {
    asm volatile(
        "mma.sync.aligned.m16n8k8.row.col.f32.tf32.tf32.f32 "
        "{%0,%1,%2,%3}, {%4,%5,%6,%7}, {%8,%9}, {%0,%1,%2,%3};"
        : "+f"(d[0]), "+f"(d[1]), "+f"(d[2]), "+f"(d[3])
        : "r"(a[0]), "r"(a[1]), "r"(a[2]), "r"(a[3]), "r"(b[0]), "r"(b[1]));
}

// ---------------------------------------------------------------------------
// tf32 mma.sync GEMM body: C[M=4096-tile, N=1024] = A * B, fp32 in/out.
// CTA 128x128, 8 warps, warp tile 64x32, K-chunk 32, triple-buffered SMEM,
// one __syncthreads per chunk. K = DMODEL = 1024 fixed.
// ---------------------------------------------------------------------------
#define GEMM_DSMEM 98304   // 3 x 16KB A + 3 x 16KB B

__device__ __forceinline__ void tgemm_body(
    const float* __restrict__ A, const float* __restrict__ B,
    float* __restrict__ C, int m0, int n0)
{
    const int N = DMODEL, K = DMODEL;
    extern __shared__ __align__(16) char dyn[];
    const uint32_t base = smem_u32(dyn);

    const int tid  = threadIdx.x;
    const int lane = tid & 31;
    const int wid  = tid >> 5;

    const int pr = lane >> 2;
    const int pc = lane & 3;
    const int MBa = wid;
    const int NBb = wid;

    const float* pA0 = A + (size_t)(m0 + MBa * 16 + pr) * K + pc;
    const float* pA1 = pA0 + (size_t)8 * K;

    float areg[16], breg[16];

    #define LDG_CHUNK(k0)                                                   \
    {                                                                       \
        _Pragma("unroll")                                                   \
        for (int q = 0; q < 4; q++) {                                       \
            int kq = (k0) + q * 8;                                          \
            areg[q * 4 + 0] = pA0[kq];                                      \
            areg[q * 4 + 1] = pA1[kq];                                      \
            areg[q * 4 + 2] = pA0[kq + 4];                                  \
            areg[q * 4 + 3] = pA1[kq + 4];                                  \
        }                                                                   \
        _Pragma("unroll")                                                   \
        for (int h = 0; h < 2; h++)                                         \
            _Pragma("unroll")                                               \
            for (int q = 0; q < 4; q++) {                                   \
                int k = (k0) + q * 8 + pc;                                  \
                int n = n0 + (NBb + 8 * h) * 8 + pr;                        \
                breg[(h * 4 + q) * 2 + 0] = B[(size_t)k * N + n];           \
                breg[(h * 4 + q) * 2 + 1] = B[(size_t)(k + 4) * N + n];     \
            }                                                               \
    }

    #define STS_CHUNK(bi)                                                   \
    {                                                                       \
        uint32_t ba = base + (uint32_t)(bi) * 16384u;                       \
        uint32_t bb = base + 49152u + (uint32_t)(bi) * 16384u;              \
        _Pragma("unroll")                                                   \
        for (int q = 0; q < 4; q++) {                                       \
            uint32_t off = ba + (uint32_t)(((q * 8 + MBa) * 128 + lane * 4) * 4); \
            uint32_t x = f2tf32(areg[q * 4 + 0]);                           \
            uint32_t y = f2tf32(areg[q * 4 + 1]);                           \
            uint32_t z = f2tf32(areg[q * 4 + 2]);                           \
            uint32_t w = f2tf32(areg[q * 4 + 3]);                           \
            asm volatile("st.shared.v4.b32 [%0], {%1,%2,%3,%4};"            \
                         :: "r"(off), "r"(x), "r"(y), "r"(z), "r"(w) : "memory"); \
        }                                                                   \
        _Pragma("unroll")                                                   \
        for (int h = 0; h < 2; h++)                                         \
            _Pragma("unroll")                                               \
            for (int q = 0; q < 4; q++) {                                   \
                uint32_t off = bb + (uint32_t)(((q * 16 + NBb + 8 * h) * 64 + lane * 2) * 4); \
                uint32_t x = f2tf32(breg[(h * 4 + q) * 2 + 0]);             \
                uint32_t y = f2tf32(breg[(h * 4 + q) * 2 + 1]);             \
                asm volatile("st.shared.v2.b32 [%0], {%1,%2};"              \
                             :: "r"(off), "r"(x), "r"(y) : "memory");       \
            }                                                               \
    }

    const int wmb = (wid & 1) * 4;
    const int wnb = (wid >> 1) * 4;

    float acc[4][4][4];
    #pragma unroll
    for (int i = 0; i < 4; i++)
        #pragma unroll
        for (int j = 0; j < 4; j++)
            #pragma unroll
            for (int r = 0; r < 4; r++) acc[i][j][r] = 0.f;

    #define MMA_CHUNK(bi)                                                   \
    {                                                                       \
        uint32_t ba = base + (uint32_t)(bi) * 16384u;                       \
        uint32_t bb = base + 49152u + (uint32_t)(bi) * 16384u;              \
        _Pragma("unroll")                                                   \
        for (int KS = 0; KS < 4; KS++) {                                    \
            uint32_t af[4][4], bf[4][2];                                    \
            _Pragma("unroll")                                               \
            for (int mb = 0; mb < 4; mb++) {                                \
                uint32_t off = ba + (uint32_t)(((KS * 8 + wmb + mb) * 128 + lane * 4) * 4); \
                asm volatile("ld.shared.v4.b32 {%0,%1,%2,%3}, [%4];"        \
                             : "=r"(af[mb][0]), "=r"(af[mb][1]),            \
                               "=r"(af[mb][2]), "=r"(af[mb][3])             \
                             : "r"(off));                                   \
            }                                                               \
            _Pragma("unroll")                                               \
            for (int nb = 0; nb < 4; nb++) {                                \
                uint32_t off = bb + (uint32_t)(((KS * 16 + wnb + nb) * 64 + lane * 2) * 4); \
                asm volatile("ld.shared.v2.b32 {%0,%1}, [%2];"              \
                             : "=r"(bf[nb][0]), "=r"(bf[nb][1]) : "r"(off));\
            }                                                               \
            _Pragma("unroll")                                               \
            for (int mb = 0; mb < 4; mb++)                                  \
                _Pragma("unroll")                                           \
                for (int nb = 0; nb < 4; nb++)                              \
                    mma_tf32(acc[mb][nb], af[mb], bf[nb]);                  \
        }                                                                   \
    }

    const int nch = K / 32;   // 32

    LDG_CHUNK(0);
    STS_CHUNK(0);
    LDG_CHUNK(32);
    __syncthreads();

    for (int c = 0; c < nch; c++) {
        if (c + 1 < nch) STS_CHUNK((c + 1) % 3);       // regs hold chunk c+1
        if (c + 2 < nch) LDG_CHUNK((c + 2) * 32);      // prefetch chunk c+2
        MMA_CHUNK(c % 3);
        __syncthreads();
    }

    #pragma unroll
    for (int mb = 0; mb < 4; mb++) {
        const int row = m0 + (wmb + mb) * 16 + (lane >> 2);
        #pragma unroll
        for (int nb = 0; nb < 4; nb++) {
            const int col = n0 + (wnb + nb) * 8 + 2 * (lane & 3);
            float2 v0 = make_float2(acc[mb][nb][0], acc[mb][nb][1]);
            float2 v1 = make_float2(acc[mb][nb][2], acc[mb][nb][3]);
            *(float2*)&C[(size_t)row * N + col]       = v0;
            *(float2*)&C[(size_t)(row + 8) * N + col] = v1;
        }
    }
    #undef LDG_CHUNK
    #undef STS_CHUNK
    #undef MMA_CHUNK
}

// Fused QKV projection: grid (24, 32). bx>>3 selects {Wq->g_Q, Wk->g_K, Wv->g_V}.
__global__ __launch_bounds__(256, 2) void qkv_kernel(
    const float* __restrict__ X,
    const float* __restrict__ Wq, const float* __restrict__ Wk,
    const float* __restrict__ Wv)
{
    const int which = blockIdx.x >> 3;
    const int n0 = (blockIdx.x & 7) * 128;
    const int m0 = blockIdx.y * 128;
    const float* B = (which == 0) ? Wq : (which == 1) ? Wk : Wv;
    float* C = (which == 0) ? g_Q : (which == 1) ? g_K : g_V;
    tgemm_body(X, B, C, m0, n0);
}

// Single GEMM (used for the Wo projection): grid (8, 32).
__global__ __launch_bounds__(256, 2) void tgemm_kernel(
    const float* __restrict__ A, const float* __restrict__ B,
    float* __restrict__ C)
{
    tgemm_body(A, B, C, blockIdx.y * 128, blockIdx.x * 128);
}

// ---------------------------------------------------------------------------
// RoPE applied in-place to g_Q and g_K.
// ---------------------------------------------------------------------------
__global__ void rope_kernel(const float* __restrict__ cosT,
                            const float* __restrict__ sinT)
{
    int idx = blockIdx.x * blockDim.x + threadIdx.x;   // over TROWS*HEADS*32
    if (idx >= TROWS * HEADS * 32) return;
    int d = idx & 31;
    int h = (idx >> 5) & (HEADS - 1);
    int t = idx >> 9;
    int s = t & (SEQ - 1);
    float c  = cosT[s * 32 + d];
    float sn = sinT[s * 32 + d];
    int base = t * DMODEL + h * DH;

    float q1 = g_Q[base + d], q2 = g_Q[base + d + 32];
    g_Q[base + d]      = q1 * c - q2 * sn;
    g_Q[base + d + 32] = q2 * c + q1 * sn;

    float k1 = g_K[base + d], k2 = g_K[base + d + 32];
    g_K[base + d]      = k1 * c - k2 * sn;
    g_K[base + d + 32] = k2 * c + k1 * sn;
}

// ---------------------------------------------------------------------------
// Tensor-core causal flash attention.  (R5 version — 65KB smem, 3 CTAs/SM)
// ---------------------------------------------------------------------------
#define ATT_DSMEM (49152 + 4*4352)   // 66560

__global__ __launch_bounds__(128) void attn_kernel()
{
    extern __shared__ __align__(16) char dynA[];
    const uint32_t Khi = smem_u32(dynA);
    const uint32_t Klo = Khi + 16384u;
    const uint32_t Vsm = Khi + 32768u;

    const int tid  = threadIdx.x;
    const int lane = tid & 31;
    const int w    = tid >> 5;
    const uint32_t Pb = Khi + 49152u + (uint32_t)w * 4352u;
    const int gid = lane >> 2;
    const int tg  = lane & 3;

    const int qt = (SEQ / 64 - 1) - blockIdx.x;   // heavy tiles first
    const int h  = blockIdx.y;
    const int b  = blockIdx.z;
    const int qbase = b * SEQ + qt * 64;

    // ---- persistent Q fragments (hi/lo split) ----
    uint32_t qhi[8][4], qlo[8][4];
    {
        const float* qp = g_Q + (size_t)(qbase + w * 16) * DMODEL + h * DH;
        #pragma unroll
        for (int kb = 0; kb < 8; kb++) {
            float v[4];
            v[0] = qp[(size_t)gid       * DMODEL + kb * 8 + tg];
            v[1] = qp[(size_t)(gid + 8) * DMODEL + kb * 8 + tg];
            v[2] = qp[(size_t)gid       * DMODEL + kb * 8 + tg + 4];
            v[3] = qp[(size_t)(gid + 8) * DMODEL + kb * 8 + tg + 4];
            #pragma unroll
            for (int i = 0; i < 4; i++) {
                qhi[kb][i] = f2tf32(v[i]);
                qlo[kb][i] = f2tf32(v[i] - __uint_as_float(qhi[kb][i]));
            }
        }
    }

    float o[8][4];
    #pragma unroll
    for (int nb = 0; nb < 8; nb++)
        #pragma unroll
        for (int c = 0; c < 4; c++) o[nb][c] = 0.f;
    float mst[2] = {-1e30f, -1e30f};
    float lst[2] = {0.f, 0.f};

    for (int kt = 0; kt <= qt; kt++) {
        const int kbase = b * SEQ + kt * 64;
        __syncthreads();

        // ---- producers: warp w fills records nb = w and w+4 ----
        #pragma unroll
        for (int nn = 0; nn < 2; nn++) {
            const int nb = w + nn * 4;
            #pragma unroll
            for (int kb = 0; kb < 8; kb++) {
                const uint32_t off = (uint32_t)((((kb * 8 + nb) * 64) + lane * 2) * 4);
                const float* kp = g_K + (size_t)(kbase + nb * 8 + gid) * DMODEL
                                      + h * DH + kb * 8 + tg;
                float k0 = kp[0], k1 = kp[4];
                uint32_t h0 = f2tf32(k0), h1 = f2tf32(k1);
                uint32_t l0 = f2tf32(k0 - __uint_as_float(h0));
                uint32_t l1 = f2tf32(k1 - __uint_as_float(h1));
                asm volatile("st.shared.v2.b32 [%0], {%1,%2};"
                             :: "r"(Khi + off), "r"(h0), "r"(h1) : "memory");
                asm volatile("st.shared.v2.b32 [%0], {%1,%2};"
                             :: "r"(Klo + off), "r"(l0), "r"(l1) : "memory");
                const float* vp = g_V + (size_t)(kbase + kb * 8 + tg) * DMODEL
                                      + h * DH + nb * 8 + gid;
                uint32_t v0 = f2tf32(vp[0]);
                uint32_t v1 = f2tf32(vp[(size_t)4 * DMODEL]);
                asm volatile("st.shared.v2.b32 [%0], {%1,%2};"
                             :: "r"(Vsm + off), "r"(v0), "r"(v1) : "memory");
            }
        }
        __syncthreads();

        // ---- S = Q K^T (3xTF32) ----
        float s[8][4];
        #pragma unroll
        for (int nb = 0; nb < 8; nb++) {
            s[nb][0] = s[nb][1] = s[nb][2] = s[nb][3] = 0.f;
            #pragma unroll
            for (int kb = 0; kb < 8; kb++) {
                const uint32_t off = (uint32_t)((((kb * 8 + nb) * 64) + lane * 2) * 4);
                uint32_t kh[2], kl[2];
                asm volatile("ld.shared.v2.b32 {%0,%1}, [%2];"
                             : "=r"(kh[0]), "=r"(kh[1]) : "r"(Khi + off));
                asm volatile("ld.shared.v2.b32 {%0,%1}, [%2];"
                             : "=r"(kl[0]), "=r"(kl[1]) : "r"(Klo + off));
                mma_tf32(s[nb], qhi[kb], kh);
                mma_tf32(s[nb], qlo[kb], kh);
                mma_tf32(s[nb], qhi[kb], kl);
            }
        }

        // ---- scale + causal mask (diagonal tile only) ----
        const bool diag = (kt == qt);
        #pragma unroll
        for (int nb = 0; nb < 8; nb++)
            #pragma unroll
            for (int c = 0; c < 4; c++) {
                s[nb][c] *= 0.125f;
                if (diag) {
                    int rl = w * 16 + gid + (c >> 1) * 8;
                    int cl = nb * 8 + 2 * tg + (c & 1);
                    if (cl > rl) s[nb][c] = -1e30f;
                }
            }

        // ---- online softmax ----
        #pragma unroll
        for (int rh = 0; rh < 2; rh++) {
            float mx = -1e30f;
            #pragma unroll
            for (int nb = 0; nb < 8; nb++)
                mx = fmaxf(mx, fmaxf(s[nb][rh * 2], s[nb][rh * 2 + 1]));
            mx = fmaxf(mx, __shfl_xor_sync(0xffffffffu, mx, 1));
            mx = fmaxf(mx, __shfl_xor_sync(0xffffffffu, mx, 2));
            float mnew  = fmaxf(mst[rh], mx);
            float alpha = __expf(mst[rh] - mnew);
            mst[rh] = mnew;
            float sum = 0.f;
            #pragma unroll
            for (int nb = 0; nb < 8; nb++) {
                float e0 = __expf(s[nb][rh * 2]     - mnew);
                float e1 = __expf(s[nb][rh * 2 + 1] - mnew);
                s[nb][rh * 2] = e0; s[nb][rh * 2 + 1] = e1;
                sum += e0 + e1;
            }
            sum += __shfl_xor_sync(0xffffffffu, sum, 1);
            sum += __shfl_xor_sync(0xffffffffu, sum, 2);
            lst[rh] = lst[rh] * alpha + sum;
            #pragma unroll
            for (int nb = 0; nb < 8; nb++) {
                o[nb][rh * 2]     *= alpha;
                o[nb][rh * 2 + 1] *= alpha;
            }
        }

        // ---- write P (tf32 bits) to padded per-warp SMEM ----
        #pragma unroll
        for (int nb = 0; nb < 8; nb++) {
            uint32_t p0 = f2tf32(s[nb][0]), p1 = f2tf32(s[nb][1]);
            uint32_t p2 = f2tf32(s[nb][2]), p3 = f2tf32(s[nb][3]);
            uint32_t o0 = Pb + (uint32_t)(((gid)     * 68 + nb * 8 + 2 * tg) * 4);
            uint32_t o1 = Pb + (uint32_t)(((gid + 8) * 68 + nb * 8 + 2 * tg) * 4);
            asm volatile("st.shared.v2.b32 [%0], {%1,%2};"
                         :: "r"(o0), "r"(p0), "r"(p1) : "memory");
            asm volatile("st.shared.v2.b32 [%0], {%1,%2};"
                         :: "r"(o1), "r"(p2), "r"(p3) : "memory");
        }
        __syncwarp();

        // ---- O += P * V ----
        #pragma unroll
        for (int kb = 0; kb < 8; kb++) {
            uint32_t a[4];
            asm volatile("ld.shared.b32 %0, [%1];" : "=r"(a[0])
                         : "r"(Pb + (uint32_t)(((gid)     * 68 + kb * 8 + tg)     * 4)));
            asm volatile("ld.shared.b32 %0, [%1];" : "=r"(a[1])
                         : "r"(Pb + (uint32_t)(((gid + 8) * 68 + kb * 8 + tg)     * 4)));
            asm volatile("ld.shared.b32 %0, [%1];" : "=r"(a[2])
                         : "r"(Pb + (uint32_t)(((gid)     * 68 + kb * 8 + tg + 4) * 4)));
            asm volatile("ld.shared.b32 %0, [%1];" : "=r"(a[3])
                         : "r"(Pb + (uint32_t)(((gid + 8) * 68 + kb * 8 + tg + 4) * 4)));
            #pragma unroll
            for (int nb = 0; nb < 8; nb++) {
                const uint32_t off = (uint32_t)((((kb * 8 + nb) * 64) + lane * 2) * 4);
                uint32_t bf[2];
                asm volatile("ld.shared.v2.b32 {%0,%1}, [%2];"
                             : "=r"(bf[0]), "=r"(bf[1]) : "r"(Vsm + off));
                mma_tf32(o[nb], a, bf);
            }
        }
        __syncwarp();
    }

    // ---- epilogue: normalize, write g_AO ----
    #pragma unroll
    for (int rh = 0; rh < 2; rh++) {
        float inv = 1.f / lst[rh];
        int row = qbase + w * 16 + gid + rh * 8;
        float* dst = g_AO + (size_t)row * DMODEL + h * DH;
        #pragma unroll
        for (int nb = 0; nb < 8; nb++)
            *(float2*)(dst + nb * 8 + 2 * tg) =
                make_float2(o[nb][rh * 2] * inv, o[nb][rh * 2 + 1] * inv);
    }
}

// ---------------------------------------------------------------------------
// kernel_launch
// ---------------------------------------------------------------------------
extern "C" void kernel_launch(void* const* d_in, const int* in_sizes, int n_in,
                              void* d_out, int out_size)
{
    const float* X    = (const float*)d_in[0];
    const float* cosT = (const float*)d_in[1];
    const float* sinT = (const float*)d_in[2];
    const float* Wq   = (const float*)d_in[4];
    const float* Wk   = (const float*)d_in[5];
    const float* Wv   = (const float*)d_in[6];
    const float* Wo   = (const float*)d_in[7];
    float* out = (float*)d_out;

    float *pAO;
    cudaGetSymbolAddress((void**)&pAO, g_AO);

    cudaFuncSetAttribute(qkv_kernel,
                         cudaFuncAttributeMaxDynamicSharedMemorySize, GEMM_DSMEM);
    cudaFuncSetAttribute(tgemm_kernel,
                         cudaFuncAttributeMaxDynamicSharedMemorySize, GEMM_DSMEM);
    cudaFuncSetAttribute(attn_kernel,
                         cudaFuncAttributeMaxDynamicSharedMemorySize, ATT_DSMEM);

    dim3 qkv_grid(24, TROWS / 128);              // (24, 32) = 768 CTAs
    qkv_kernel<<<qkv_grid, 256, GEMM_DSMEM>>>(X, Wq, Wk, Wv);

    int rope_total = TROWS * HEADS * 32;
    rope_kernel<<<(rope_total + 255) / 256, 256>>>(cosT, sinT);

    dim3 attn_grid(SEQ / 64, HEADS, BATCH);      // (32, 16, 2)
    attn_kernel<<<attn_grid, 128, ATT_DSMEM>>>();

    dim3 gemm_grid(DMODEL / 128, TROWS / 128);   // (8, 32)
    tgemm_kernel<<<gemm_grid, 256, GEMM_DSMEM>>>(pAO, Wo, out);

    (void)in_sizes; (void)n_in; (void)out_size;
}

// round 13
// speedup vs baseline: 1.4061x; 1.0835x over previous
#include <cuda_runtime.h>
#include <cstdint>
#include <math.h>

// Problem constants
#define DMODEL 1024
#define HEADS  16
#define DH     64
#define SEQ    2048
#define BATCH  2
#define TROWS  (BATCH*SEQ)   // 4096

// Scratch (allocation-free rule: __device__ globals)
__device__ float g_Q[TROWS*DMODEL];
__device__ float g_K[TROWS*DMODEL];
__device__ float g_V[TROWS*DMODEL];
__device__ float g_AO[TROWS*DMODEL];

// ---------------------------------------------------------------------------
// Helpers
// ---------------------------------------------------------------------------
__device__ __forceinline__ uint32_t smem_u32(const void* p) {
    uint32_t a;
    asm("{ .reg .u64 t; cvta.to.shared.u64 t, %1; cvt.u32.u64 %0, t; }"
        : "=r"(a) : "l"(p));
    return a;
}
__device__ __forceinline__ uint32_t f2tf32(float f) {
    uint32_t r;
    asm("cvt.rna.tf32.f32 %0, %1;" : "=r"(r) : "f"(f));
    return r;
}
__device__ __forceinline__ void mma_tf32(float* d, const uint32_t* a,
                                         const uint32_t* b) {
    asm volatile(
        "mma.sync.aligned.m16n8k8.row.col.f32.tf32.tf32.f32 "
        "{%0,%1,%2,%3}, {%4,%5,%6,%7}, {%8,%9}, {%0,%1,%2,%3};"
        : "+f"(d[0]), "+f"(d[1]), "+f"(d[2]), "+f"(d[3])
        : "r"(a[0]), "r"(a[1]), "r"(a[2]), "r"(a[3]), "r"(b[0]), "r"(b[1]));
}
__device__ __forceinline__ uint32_t lds32(uint32_t addr) {
    uint32_t v;
    asm volatile("ld.shared.b32 %0, [%1];" : "=r"(v) : "r"(addr));
    return v;
}

// ---------------------------------------------------------------------------
// tf32 mma.sync GEMM body: C = A[M,K]*B[K,N], fp32 in/out. K = N = 1024.
// CTA 128x128, 8 warps, warp tile 64x32, K-chunk 32, triple-buffered SMEM,
// one __syncthreads per chunk.
// R12: natural-layout swizzled SMEM tiles; all LDG/STS are float4 and dense.
//   A tile [row128][k32] pitch 128B, 16B-unit swizzle: unit' = (k>>2)^(row&7)
//   B tile [k32][n128]  pitch 512B, swizzle: n' = n ^ ((k&3)*8)
// Fragments gathered with conflict-free LDS.32 (bank sets verified).
// ---------------------------------------------------------------------------
#define GEMM_DSMEM 98304   // 3 x 16KB A + 3 x 16KB B

__device__ __forceinline__ void tgemm_body(
    const float* __restrict__ A, const float* __restrict__ B,
    float* __restrict__ C, int m0, int n0)
{
    const int N = DMODEL, K = DMODEL;
    extern __shared__ __align__(16) char dyn[];
    const uint32_t base = smem_u32(dyn);
    // A buffers at base + bi*16384; B buffers at base + 49152 + bi*16384

    const int tid  = threadIdx.x;
    const int lane = tid & 31;
    const int wid  = tid >> 5;

    // producer geometry: thread -> (row/k-row = tid>>3, 16B column = (tid&7)*4)
    const int par = tid >> 3;          // 0..31
    const int pac = (tid & 7) * 4;     // 0..28

    float4 areg[4], breg[4];

    #define LDG_CHUNK(k0)                                                    \
    {                                                                        \
        _Pragma("unroll")                                                    \
        for (int q = 0; q < 4; q++) {                                        \
            areg[q] = *(const float4*)(A + (size_t)(m0 + par + 32 * q) * K   \
                                         + (k0) + pac);                      \
            breg[q] = *(const float4*)(B + (size_t)((k0) + par) * N          \
                                         + n0 + pac + 32 * q);               \
        }                                                                    \
    }

    // A store: row = par+32q (row&7 = par&7), unit' = (pac>>2)^(par&7)
    // B store: k = par, n' = (pac+32q) ^ ((par&3)*8)  (contiguity preserved)
    #define STS_CHUNK(bi)                                                    \
    {                                                                        \
        uint32_t ba = base + (uint32_t)(bi) * 16384u;                        \
        uint32_t bb = base + 49152u + (uint32_t)(bi) * 16384u;               \
        uint32_t ua = ba + (uint32_t)(par * 128 + (((pac >> 2) ^ (par & 7)) << 4)); \
        uint32_t ub = bb + (uint32_t)(par * 512 + ((pac ^ ((par & 3) * 8)) * 4)); \
        _Pragma("unroll")                                                    \
        for (int q = 0; q < 4; q++) {                                        \
            uint32_t x = f2tf32(areg[q].x), y = f2tf32(areg[q].y);           \
            uint32_t z = f2tf32(areg[q].z), w = f2tf32(areg[q].w);           \
            asm volatile("st.shared.v4.b32 [%0], {%1,%2,%3,%4};"             \
                         :: "r"(ua + (uint32_t)(q * 32 * 128)),              \
                            "r"(x), "r"(y), "r"(z), "r"(w) : "memory");      \
            x = f2tf32(breg[q].x); y = f2tf32(breg[q].y);                    \
            z = f2tf32(breg[q].z); w = f2tf32(breg[q].w);                    \
            asm volatile("st.shared.v4.b32 [%0], {%1,%2,%3,%4};"             \
                         :: "r"(ub + (uint32_t)(q * 32 * 4)),                \
                            "r"(x), "r"(y), "r"(z), "r"(w) : "memory");      \
        }                                                                    \
    }

    // consumer geometry
    const int gid = lane >> 2;   // 0..7
    const int tg  = lane & 3;    // 0..3
    const int wmb = (wid & 1) * 4;
    const int wnb = (wid >> 1) * 4;

    float acc[4][4][4];
    #pragma unroll
    for (int i = 0; i < 4; i++)
        #pragma unroll
        for (int j = 0; j < 4; j++)
            #pragma unroll
            for (int r = 0; r < 4; r++) acc[i][j][r] = 0.f;

    // a0/a1/a2/a3: row = (wmb+mb)*16 + gid (+8); k-unit = (2KS+h)^gid; word+tg
    // b0/b1: k-row = KS*8+tg (+4); n-word = ((wnb+nb)*8+gid) ^ (tg*8)
    #define MMA_CHUNK(bi)                                                    \
    {                                                                        \
        uint32_t ba = base + (uint32_t)(bi) * 16384u;                        \
        uint32_t bb = base + 49152u + (uint32_t)(bi) * 16384u;               \
        _Pragma("unroll")                                                    \
        for (int KS = 0; KS < 4; KS++) {                                     \
            uint32_t af[4][4], bf[4][2];                                     \
            _Pragma("unroll")                                                \
            for (int mb = 0; mb < 4; mb++) {                                 \
                uint32_t r0 = ba + (uint32_t)(((wmb + mb) * 16 + gid) * 128);\
                uint32_t u0 = (uint32_t)(((((2 * KS)     ^ gid) << 2) + tg) * 4); \
                uint32_t u1 = (uint32_t)(((((2 * KS + 1) ^ gid) << 2) + tg) * 4); \
                af[mb][0] = lds32(r0 + u0);                                  \
                af[mb][1] = lds32(r0 + 1024u + u0);                          \
                af[mb][2] = lds32(r0 + u1);                                  \
                af[mb][3] = lds32(r0 + 1024u + u1);                          \
            }                                                                \
            _Pragma("unroll")                                                \
            for (int nb = 0; nb < 4; nb++) {                                 \
                uint32_t nw = (uint32_t)((((wnb + nb) * 8 + gid) ^ (tg * 8)) * 4); \
                uint32_t k0b = bb + (uint32_t)((KS * 8 + tg) * 512);         \
                bf[nb][0] = lds32(k0b + nw);                                 \
                bf[nb][1] = lds32(k0b + 2048u + nw);                         \
            }                                                                \
            _Pragma("unroll")                                                \
            for (int mb = 0; mb < 4; mb++)                                   \
                _Pragma("unroll")                                            \
                for (int nb = 0; nb < 4; nb++)                               \
                    mma_tf32(acc[mb][nb], af[mb], bf[nb]);                   \
        }                                                                    \
    }

    const int nch = K / 32;   // 32

    LDG_CHUNK(0);
    STS_CHUNK(0);
    LDG_CHUNK(32);
    __syncthreads();

    for (int c = 0; c < nch; c++) {
        if (c + 1 < nch) STS_CHUNK((c + 1) % 3);       // regs hold chunk c+1
        if (c + 2 < nch) LDG_CHUNK((c + 2) * 32);      // prefetch chunk c+2
        MMA_CHUNK(c % 3);
        __syncthreads();
    }

    #pragma unroll
    for (int mb = 0; mb < 4; mb++) {
        const int row = m0 + (wmb + mb) * 16 + gid;
        #pragma unroll
        for (int nb = 0; nb < 4; nb++) {
            const int col = n0 + (wnb + nb) * 8 + 2 * tg;
            float2 v0 = make_float2(acc[mb][nb][0], acc[mb][nb][1]);
            float2 v1 = make_float2(acc[mb][nb][2], acc[mb][nb][3]);
            *(float2*)&C[(size_t)row * N + col]       = v0;
            *(float2*)&C[(size_t)(row + 8) * N + col] = v1;
        }
    }
    #undef LDG_CHUNK
    #undef STS_CHUNK
    #undef MMA_CHUNK
}

// Fused QKV projection: grid (24, 32). bx>>3 selects {Wq->g_Q, Wk->g_K, Wv->g_V}.
__global__ __launch_bounds__(256, 2) void qkv_kernel(
    const float* __restrict__ X,
    const float* __restrict__ Wq, const float* __restrict__ Wk,
    const float* __restrict__ Wv)
{
    const int which = blockIdx.x >> 3;
    const int n0 = (blockIdx.x & 7) * 128;
    const int m0 = blockIdx.y * 128;
    const float* B = (which == 0) ? Wq : (which == 1) ? Wk : Wv;
    float* C = (which == 0) ? g_Q : (which == 1) ? g_K : g_V;
    tgemm_body(X, B, C, m0, n0);
}

// Single GEMM (used for the Wo projection): grid (8, 32).
__global__ __launch_bounds__(256, 2) void tgemm_kernel(
    const float* __restrict__ A, const float* __restrict__ B,
    float* __restrict__ C)
{
    tgemm_body(A, B, C, blockIdx.y * 128, blockIdx.x * 128);
}

// ---------------------------------------------------------------------------
// RoPE applied in-place to g_Q and g_K.
// ---------------------------------------------------------------------------
__global__ void rope_kernel(const float* __restrict__ cosT,
                            const float* __restrict__ sinT)
{
    int idx = blockIdx.x * blockDim.x + threadIdx.x;   // over TROWS*HEADS*32
    if (idx >= TROWS * HEADS * 32) return;
    int d = idx & 31;
    int h = (idx >> 5) & (HEADS - 1);
    int t = idx >> 9;
    int s = t & (SEQ - 1);
    float c  = cosT[s * 32 + d];
    float sn = sinT[s * 32 + d];
    int base = t * DMODEL + h * DH;

    float q1 = g_Q[base + d], q2 = g_Q[base + d + 32];
    g_Q[base + d]      = q1 * c - q2 * sn;
    g_Q[base + d + 32] = q2 * c + q1 * sn;

    float k1 = g_K[base + d], k2 = g_K[base + d + 32];
    g_K[base + d]      = k1 * c - k2 * sn;
    g_K[base + d + 32] = k2 * c + k1 * sn;
}

// ---------------------------------------------------------------------------
// Tensor-core causal flash attention.  (unchanged — 65KB smem, 3 CTAs/SM)
// ---------------------------------------------------------------------------
#define ATT_DSMEM (49152 + 4*4352)   // 66560

__global__ __launch_bounds__(128) void attn_kernel()
{
    extern __shared__ __align__(16) char dynA[];
    const uint32_t Khi = smem_u32(dynA);
    const uint32_t Klo = Khi + 16384u;
    const uint32_t Vsm = Khi + 32768u;

    const int tid  = threadIdx.x;
    const int lane = tid & 31;
    const int w    = tid >> 5;
    const uint32_t Pb = Khi + 49152u + (uint32_t)w * 4352u;
    const int gid = lane >> 2;
    const int tg  = lane & 3;

    const int qt = (SEQ / 64 - 1) - blockIdx.x;   // heavy tiles first
    const int h  = blockIdx.y;
    const int b  = blockIdx.z;
    const int qbase = b * SEQ + qt * 64;

    // ---- persistent Q fragments (hi/lo split) ----
    uint32_t qhi[8][4], qlo[8][4];
    {
        const float* qp = g_Q + (size_t)(qbase + w * 16) * DMODEL + h * DH;
        #pragma unroll
        for (int kb = 0; kb < 8; kb++) {
            float v[4];
            v[0] = qp[(size_t)gid       * DMODEL + kb * 8 + tg];
            v[1] = qp[(size_t)(gid + 8) * DMODEL + kb * 8 + tg];
            v[2] = qp[(size_t)gid       * DMODEL + kb * 8 + tg + 4];
            v[3] = qp[(size_t)(gid + 8) * DMODEL + kb * 8 + tg + 4];
            #pragma unroll
            for (int i = 0; i < 4; i++) {
                qhi[kb][i] = f2tf32(v[i]);
                qlo[kb][i] = f2tf32(v[i] - __uint_as_float(qhi[kb][i]));
            }
        }
    }

    float o[8][4];
    #pragma unroll
    for (int nb = 0; nb < 8; nb++)
        #pragma unroll
        for (int c = 0; c < 4; c++) o[nb][c] = 0.f;
    float mst[2] = {-1e30f, -1e30f};
    float lst[2] = {0.f, 0.f};

    for (int kt = 0; kt <= qt; kt++) {
        const int kbase = b * SEQ + kt * 64;
        __syncthreads();

        // ---- producers: warp w fills records nb = w and w+4 ----
        #pragma unroll
        for (int nn = 0; nn < 2; nn++) {
            const int nb = w + nn * 4;
            #pragma unroll
            for (int kb = 0; kb < 8; kb++) {
                const uint32_t off = (uint32_t)((((kb * 8 + nb) * 64) + lane * 2) * 4);
                const float* kp = g_K + (size_t)(kbase + nb * 8 + gid) * DMODEL
                                      + h * DH + kb * 8 + tg;
                float k0 = kp[0], k1 = kp[4];
                uint32_t h0 = f2tf32(k0), h1 = f2tf32(k1);
                uint32_t l0 = f2tf32(k0 - __uint_as_float(h0));
                uint32_t l1 = f2tf32(k1 - __uint_as_float(h1));
                asm volatile("st.shared.v2.b32 [%0], {%1,%2};"
                             :: "r"(Khi + off), "r"(h0), "r"(h1) : "memory");
                asm volatile("st.shared.v2.b32 [%0], {%1,%2};"
                             :: "r"(Klo + off), "r"(l0), "r"(l1) : "memory");
                const float* vp = g_V + (size_t)(kbase + kb * 8 + tg) * DMODEL
                                      + h * DH + nb * 8 + gid;
                uint32_t v0 = f2tf32(vp[0]);
                uint32_t v1 = f2tf32(vp[(size_t)4 * DMODEL]);
                asm volatile("st.shared.v2.b32 [%0], {%1,%2};"
                             :: "r"(Vsm + off), "r"(v0), "r"(v1) : "memory");
            }
        }
        __syncthreads();

        // ---- S = Q K^T (3xTF32) ----
        float s[8][4];
        #pragma unroll
        for (int nb = 0; nb < 8; nb++) {
            s[nb][0] = s[nb][1] = s[nb][2] = s[nb][3] = 0.f;
            #pragma unroll
            for (int kb = 0; kb < 8; kb++) {
                const uint32_t off = (uint32_t)((((kb * 8 + nb) * 64) + lane * 2) * 4);
                uint32_t kh[2], kl[2];
                asm volatile("ld.shared.v2.b32 {%0,%1}, [%2];"
                             : "=r"(kh[0]), "=r"(kh[1]) : "r"(Khi + off));
                asm volatile("ld.shared.v2.b32 {%0,%1}, [%2];"
                             : "=r"(kl[0]), "=r"(kl[1]) : "r"(Klo + off));
                mma_tf32(s[nb], qhi[kb], kh);
                mma_tf32(s[nb], qlo[kb], kh);
                mma_tf32(s[nb], qhi[kb], kl);
            }
        }

        // ---- scale + causal mask (diagonal tile only) ----
        const bool diag = (kt == qt);
        #pragma unroll
        for (int nb = 0; nb < 8; nb++)
            #pragma unroll
            for (int c = 0; c < 4; c++) {
                s[nb][c] *= 0.125f;
                if (diag) {
                    int rl = w * 16 + gid + (c >> 1) * 8;
                    int cl = nb * 8 + 2 * tg + (c & 1);
                    if (cl > rl) s[nb][c] = -1e30f;
                }
            }

        // ---- online softmax ----
        #pragma unroll
        for (int rh = 0; rh < 2; rh++) {
            float mx = -1e30f;
            #pragma unroll
            for (int nb = 0; nb < 8; nb++)
                mx = fmaxf(mx, fmaxf(s[nb][rh * 2], s[nb][rh * 2 + 1]));
            mx = fmaxf(mx, __shfl_xor_sync(0xffffffffu, mx, 1));
            mx = fmaxf(mx, __shfl_xor_sync(0xffffffffu, mx, 2));
            float mnew  = fmaxf(mst[rh], mx);
            float alpha = __expf(mst[rh] - mnew);
            mst[rh] = mnew;
            float sum = 0.f;
            #pragma unroll
            for (int nb = 0; nb < 8; nb++) {
                float e0 = __expf(s[nb][rh * 2]     - mnew);
                float e1 = __expf(s[nb][rh * 2 + 1] - mnew);
                s[nb][rh * 2] = e0; s[nb][rh * 2 + 1] = e1;
                sum += e0 + e1;
            }
            sum += __shfl_xor_sync(0xffffffffu, sum, 1);
            sum += __shfl_xor_sync(0xffffffffu, sum, 2);
            lst[rh] = lst[rh] * alpha + sum;
            #pragma unroll
            for (int nb = 0; nb < 8; nb++) {
                o[nb][rh * 2]     *= alpha;
                o[nb][rh * 2 + 1] *= alpha;
            }
        }

        // ---- write P (tf32 bits) to padded per-warp SMEM ----
        #pragma unroll
        for (int nb = 0; nb < 8; nb++) {
            uint32_t p0 = f2tf32(s[nb][0]), p1 = f2tf32(s[nb][1]);
            uint32_t p2 = f2tf32(s[nb][2]), p3 = f2tf32(s[nb][3]);
            uint32_t o0 = Pb + (uint32_t)(((gid)     * 68 + nb * 8 + 2 * tg) * 4);
            uint32_t o1 = Pb + (uint32_t)(((gid + 8) * 68 + nb * 8 + 2 * tg) * 4);
            asm volatile("st.shared.v2.b32 [%0], {%1,%2};"
                         :: "r"(o0), "r"(p0), "r"(p1) : "memory");
            asm volatile("st.shared.v2.b32 [%0], {%1,%2};"
                         :: "r"(o1), "r"(p2), "r"(p3) : "memory");
        }
        __syncwarp();

        // ---- O += P * V ----
        #pragma unroll
        for (int kb = 0; kb < 8; kb++) {
            uint32_t a[4];
            a[0] = lds32(Pb + (uint32_t)(((gid)     * 68 + kb * 8 + tg)     * 4));
            a[1] = lds32(Pb + (uint32_t)(((gid + 8) * 68 + kb * 8 + tg)     * 4));
            a[2] = lds32(Pb + (uint32_t)(((gid)     * 68 + kb * 8 + tg + 4) * 4));
            a[3] = lds32(Pb + (uint32_t)(((gid + 8) * 68 + kb * 8 + tg + 4) * 4));
            #pragma unroll
            for (int nb = 0; nb < 8; nb++) {
                const uint32_t off = (uint32_t)((((kb * 8 + nb) * 64) + lane * 2) * 4);
                uint32_t bf[2];
                asm volatile("ld.shared.v2.b32 {%0,%1}, [%2];"
                             : "=r"(bf[0]), "=r"(bf[1]) : "r"(Vsm + off));
                mma_tf32(o[nb], a, bf);
            }
        }
        __syncwarp();
    }

    // ---- epilogue: normalize, write g_AO ----
    #pragma unroll
    for (int rh = 0; rh < 2; rh++) {
        float inv = 1.f / lst[rh];
        int row = qbase + w * 16 + gid + rh * 8;
        float* dst = g_AO + (size_t)row * DMODEL + h * DH;
        #pragma unroll
        for (int nb = 0; nb < 8; nb++)
            *(float2*)(dst + nb * 8 + 2 * tg) =
                make_float2(o[nb][rh * 2] * inv, o[nb][rh * 2 + 1] * inv);
    }
}

// ---------------------------------------------------------------------------
// kernel_launch
// ---------------------------------------------------------------------------
extern "C" void kernel_launch(void* const* d_in, const int* in_sizes, int n_in,
                              void* d_out, int out_size)
{
    const float* X    = (const float*)d_in[0];
    const float* cosT = (const float*)d_in[1];
    const float* sinT = (const float*)d_in[2];
    const float* Wq   = (const float*)d_in[4];
    const float* Wk   = (const float*)d_in[5];
    const float* Wv   = (const float*)d_in[6];
    const float* Wo   = (const float*)d_in[7];
    float* out = (float*)d_out;

    float *pAO;
    cudaGetSymbolAddress((void**)&pAO, g_AO);

    cudaFuncSetAttribute(qkv_kernel,
                         cudaFuncAttributeMaxDynamicSharedMemorySize, GEMM_DSMEM);
    cudaFuncSetAttribute(tgemm_kernel,
                         cudaFuncAttributeMaxDynamicSharedMemorySize, GEMM_DSMEM);
    cudaFuncSetAttribute(attn_kernel,
                         cudaFuncAttributeMaxDynamicSharedMemorySize, ATT_DSMEM);

    dim3 qkv_grid(24, TROWS / 128);              // (24, 32) = 768 CTAs
    qkv_kernel<<<qkv_grid, 256, GEMM_DSMEM>>>(X, Wq, Wk, Wv);

    int rope_total = TROWS * HEADS * 32;
    rope_kernel<<<(rope_total + 255) / 256, 256>>>(cosT, sinT);

    dim3 attn_grid(SEQ / 64, HEADS, BATCH);      // (32, 16, 2)
    attn_kernel<<<attn_grid, 128, ATT_DSMEM>>>();

    dim3 gemm_grid(DMODEL / 128, TROWS / 128);   // (8, 32)
    tgemm_kernel<<<gemm_grid, 256, GEMM_DSMEM>>>(pAO, Wo, out);

    (void)in_sizes; (void)n_in; (void)out_size;
}

// round 14
// speedup vs baseline: 1.4300x; 1.0170x over previous
#include <cuda_runtime.h>
#include <cstdint>
#include <math.h>

// Problem constants
#define DMODEL 1024
#define HEADS  16
#define DH     64
#define SEQ    2048
#define BATCH  2
#define TROWS  (BATCH*SEQ)   // 4096

// Scratch (allocation-free rule: __device__ globals)
__device__ float g_Q[TROWS*DMODEL];
__device__ float g_K[TROWS*DMODEL];
__device__ float g_V[TROWS*DMODEL];
__device__ float g_AO[TROWS*DMODEL];      // written tf32-exact by attn epilogue
__device__ float g_Xr[TROWS*DMODEL];      // tf32-rounded X
__device__ float g_Wqr[DMODEL*DMODEL];
__device__ float g_Wkr[DMODEL*DMODEL];
__device__ float g_Wvr[DMODEL*DMODEL];
__device__ float g_Wor[DMODEL*DMODEL];
// K/V fragment records per (b,h,ktile): 4096 words each
#define NTILES (BATCH*HEADS*(SEQ/64))    // 1024
__device__ float g_KhiR[NTILES*4096];
__device__ float g_KloR[NTILES*4096];
__device__ float g_VR  [NTILES*4096];

// ---------------------------------------------------------------------------
// Helpers
// ---------------------------------------------------------------------------
__device__ __forceinline__ uint32_t smem_u32(const void* p) {
    uint32_t a;
    asm("{ .reg .u64 t; cvta.to.shared.u64 t, %1; cvt.u32.u64 %0, t; }"
        : "=r"(a) : "l"(p));
    return a;
}
__device__ __forceinline__ uint32_t f2tf32(float f) {
    uint32_t r;
    asm("cvt.rna.tf32.f32 %0, %1;" : "=r"(r) : "f"(f));
    return r;
}
__device__ __forceinline__ void mma_tf32(float* d, const uint32_t* a,
                                         const uint32_t* b) {
    asm volatile(
        "mma.sync.aligned.m16n8k8.row.col.f32.tf32.tf32.f32 "
        "{%0,%1,%2,%3}, {%4,%5,%6,%7}, {%8,%9}, {%0,%1,%2,%3};"
        : "+f"(d[0]), "+f"(d[1]), "+f"(d[2]), "+f"(d[3])
        : "r"(a[0]), "r"(a[1]), "r"(a[2]), "r"(a[3]), "r"(b[0]), "r"(b[1]));
}
__device__ __forceinline__ uint32_t lds32(uint32_t addr) {
    uint32_t v;
    asm volatile("ld.shared.b32 %0, [%1];" : "=r"(v) : "r"(addr));
    return v;
}
#define CP16(dst, src) \
    asm volatile("cp.async.cg.shared.global [%0], [%1], 16;" \
                 :: "r"(dst), "l"(src) : "memory")
#define CP_COMMIT() asm volatile("cp.async.commit_group;" ::: "memory")
#define CP_WAIT(n)  asm volatile("cp.async.wait_group %0;" :: "n"(n) : "memory")

// ---------------------------------------------------------------------------
// Elementwise tf32 rounding pass: dst = rna_tf32(src), stored as f32 bits.
// ---------------------------------------------------------------------------
__global__ void round_kernel(const float4* __restrict__ src,
                             float4* __restrict__ dst, int n4)
{
    int i = blockIdx.x * blockDim.x + threadIdx.x;
    if (i >= n4) return;
    float4 v = src[i];
    dst[i] = make_float4(__uint_as_float(f2tf32(v.x)),
                         __uint_as_float(f2tf32(v.y)),
                         __uint_as_float(f2tf32(v.z)),
                         __uint_as_float(f2tf32(v.w)));
}

// ---------------------------------------------------------------------------
// tf32 mma.sync GEMM body: C = A[M,K]*B[K,N], f32 bits holding tf32-exact
// values (pre-rounded). CTA 128x128, 8 warps, warp tile 64x32, K-chunk 32.
// R14: cp.async.cg producers into the 3-stage swizzled SMEM ring; one
// __syncthreads per chunk. Consumer LDS pattern unchanged from R12.
// ---------------------------------------------------------------------------
#define GEMM_DSMEM 98304   // 3 x 16KB A + 3 x 16KB B

__device__ __forceinline__ void tgemm_body(
    const float* __restrict__ A, const float* __restrict__ B,
    float* __restrict__ C, int m0, int n0)
{
    const int N = DMODEL, K = DMODEL;
    extern __shared__ __align__(16) char dyn[];
    const uint32_t base = smem_u32(dyn);

    const int tid  = threadIdx.x;
    const int lane = tid & 31;
    const int wid  = tid >> 5;

    // producer geometry
    const int par = tid >> 3;          // 0..31
    const int pac = (tid & 7) * 4;     // 0..28
    const uint32_t ua_off = (uint32_t)(par * 128 + (((pac >> 2) ^ (par & 7)) << 4));
    const uint32_t ub_off = (uint32_t)(par * 512 + ((pac ^ ((par & 3) * 8)) * 4));
    const float* pAsrc = A + (size_t)(m0 + par) * K + pac;
    const float* pBsrc = B + (size_t)par * N + n0 + pac;

    #define CPA_CHUNK(k0, bi)                                                \
    {                                                                        \
        uint32_t ua = base + (uint32_t)(bi) * 16384u + ua_off;               \
        uint32_t ub = base + 49152u + (uint32_t)(bi) * 16384u + ub_off;      \
        _Pragma("unroll")                                                    \
        for (int q = 0; q < 4; q++) {                                        \
            CP16(ua + (uint32_t)(q * 4096), pAsrc + (size_t)(32 * q) * K + (k0)); \
            CP16(ub + (uint32_t)(q * 128),  pBsrc + (size_t)(k0) * N + 32 * q);   \
        }                                                                    \
        CP_COMMIT();                                                         \
    }

    // consumer geometry
    const int gid = lane >> 2;
    const int tg  = lane & 3;
    const int wmb = (wid & 1) * 4;
    const int wnb = (wid >> 1) * 4;

    float acc[4][4][4];
    #pragma unroll
    for (int i = 0; i < 4; i++)
        #pragma unroll
        for (int j = 0; j < 4; j++)
            #pragma unroll
            for (int r = 0; r < 4; r++) acc[i][j][r] = 0.f;

    #define MMA_CHUNK(bi)                                                    \
    {                                                                        \
        uint32_t ba = base + (uint32_t)(bi) * 16384u;                        \
        uint32_t bb = base + 49152u + (uint32_t)(bi) * 16384u;               \
        _Pragma("unroll")                                                    \
        for (int KS = 0; KS < 4; KS++) {                                     \
            uint32_t af[4][4], bf[4][2];                                     \
            _Pragma("unroll")                                                \
            for (int mb = 0; mb < 4; mb++) {                                 \
                uint32_t r0 = ba + (uint32_t)(((wmb + mb) * 16 + gid) * 128);\
                uint32_t u0 = (uint32_t)(((((2 * KS)     ^ gid) << 2) + tg) * 4); \
                uint32_t u1 = (uint32_t)(((((2 * KS + 1) ^ gid) << 2) + tg) * 4); \
                af[mb][0] = lds32(r0 + u0);                                  \
                af[mb][1] = lds32(r0 + 1024u + u0);                          \
                af[mb][2] = lds32(r0 + u1);                                  \
                af[mb][3] = lds32(r0 + 1024u + u1);                          \
            }                                                                \
            _Pragma("unroll")                                                \
            for (int nb = 0; nb < 4; nb++) {                                 \
                uint32_t nw = (uint32_t)((((wnb + nb) * 8 + gid) ^ (tg * 8)) * 4); \
                uint32_t k0b = bb + (uint32_t)((KS * 8 + tg) * 512);         \
                bf[nb][0] = lds32(k0b + nw);                                 \
                bf[nb][1] = lds32(k0b + 2048u + nw);                         \
            }                                                                \
            _Pragma("unroll")                                                \
            for (int mb = 0; mb < 4; mb++)                                   \
                _Pragma("unroll")                                            \
                for (int nb = 0; nb < 4; nb++)                               \
                    mma_tf32(acc[mb][nb], af[mb], bf[nb]);                   \
        }                                                                    \
    }

    const int nch = K / 32;   // 32

    CPA_CHUNK(0, 0);
    CPA_CHUNK(32, 1);

    for (int c = 0; c < nch; c++) {
        if (c < nch - 1) { CP_WAIT(1); } else { CP_WAIT(0); }
        __syncthreads();                      // stage c visible; prev MMA done
        if (c + 2 < nch) CPA_CHUNK((c + 2) * 32, (c + 2) % 3);
        MMA_CHUNK(c % 3);
    }

    #pragma unroll
    for (int mb = 0; mb < 4; mb++) {
        const int row = m0 + (wmb + mb) * 16 + gid;
        #pragma unroll
        for (int nb = 0; nb < 4; nb++) {
            const int col = n0 + (wnb + nb) * 8 + 2 * tg;
            float2 v0 = make_float2(acc[mb][nb][0], acc[mb][nb][1]);
            float2 v1 = make_float2(acc[mb][nb][2], acc[mb][nb][3]);
            *(float2*)&C[(size_t)row * N + col]       = v0;
            *(float2*)&C[(size_t)(row + 8) * N + col] = v1;
        }
    }
    #undef CPA_CHUNK
    #undef MMA_CHUNK
}

// Fused QKV projection: grid (24, 32).
__global__ __launch_bounds__(256, 2) void qkv_kernel()
{
    const int which = blockIdx.x >> 3;
    const int n0 = (blockIdx.x & 7) * 128;
    const int m0 = blockIdx.y * 128;
    const float* B = (which == 0) ? g_Wqr : (which == 1) ? g_Wkr : g_Wvr;
    float* C = (which == 0) ? g_Q : (which == 1) ? g_K : g_V;
    tgemm_body(g_Xr, B, C, m0, n0);
}

// Single GEMM (Wo projection): grid (8, 32).
__global__ __launch_bounds__(256, 2) void tgemm_kernel(float* __restrict__ out)
{
    tgemm_body(g_AO, g_Wor, out, blockIdx.y * 128, blockIdx.x * 128);
}

// ---------------------------------------------------------------------------
// RoPE applied in-place to g_Q and g_K.
// ---------------------------------------------------------------------------
__global__ void rope_kernel(const float* __restrict__ cosT,
                            const float* __restrict__ sinT)
{
    int idx = blockIdx.x * blockDim.x + threadIdx.x;
    if (idx >= TROWS * HEADS * 32) return;
    int d = idx & 31;
    int h = (idx >> 5) & (HEADS - 1);
    int t = idx >> 9;
    int s = t & (SEQ - 1);
    float c  = cosT[s * 32 + d];
    float sn = sinT[s * 32 + d];
    int base = t * DMODEL + h * DH;

    float q1 = g_Q[base + d], q2 = g_Q[base + d + 32];
    g_Q[base + d]      = q1 * c - q2 * sn;
    g_Q[base + d + 32] = q2 * c + q1 * sn;

    float k1 = g_K[base + d], k2 = g_K[base + d + 32];
    g_K[base + d]      = k1 * c - k2 * sn;
    g_K[base + d + 32] = k2 * c + k1 * sn;
}

// ---------------------------------------------------------------------------
// Record builder: converts roped K and V into mma B-fragment records ONCE
// per (b,h,ktile). Grid (32, 16, 2), 128 threads (4 warps); same geometry
// as the old in-loop producer, writing to global instead of SMEM.
// ---------------------------------------------------------------------------
__global__ __launch_bounds__(128) void record_kernel()
{
    const int tid  = threadIdx.x;
    const int lane = tid & 31;
    const int w    = tid >> 5;
    const int gid  = lane >> 2;
    const int tg   = lane & 3;
    const int kt = blockIdx.x, h = blockIdx.y, b = blockIdx.z;
    const int kbase = b * SEQ + kt * 64;
    const size_t tile = ((size_t)(b * HEADS + h) * (SEQ / 64) + kt) * 4096;
    float* dH = g_KhiR + tile;
    float* dL = g_KloR + tile;
    float* dV = g_VR   + tile;

    #pragma unroll
    for (int nn = 0; nn < 2; nn++) {
        const int nb = w + nn * 4;
        #pragma unroll
        for (int kb = 0; kb < 8; kb++) {
            const int off = ((kb * 8 + nb) * 64) + lane * 2;
            const float* kp = g_K + (size_t)(kbase + nb * 8 + gid) * DMODEL
                                  + h * DH + kb * 8 + tg;
            float k0 = kp[0], k1 = kp[4];
            uint32_t h0 = f2tf32(k0), h1 = f2tf32(k1);
            uint32_t l0 = f2tf32(k0 - __uint_as_float(h0));
            uint32_t l1 = f2tf32(k1 - __uint_as_float(h1));
            *(float2*)(dH + off) = make_float2(__uint_as_float(h0), __uint_as_float(h1));
            *(float2*)(dL + off) = make_float2(__uint_as_float(l0), __uint_as_float(l1));
            const float* vp = g_V + (size_t)(kbase + kb * 8 + tg) * DMODEL
                                  + h * DH + nb * 8 + gid;
            uint32_t v0 = f2tf32(vp[0]);
            uint32_t v1 = f2tf32(vp[(size_t)4 * DMODEL]);
            *(float2*)(dV + off) = make_float2(__uint_as_float(v0), __uint_as_float(v1));
        }
    }
}

// ---------------------------------------------------------------------------
// Tensor-core causal flash attention.  (65KB smem, 3 CTAs/SM)
// R14: per-tile producer is a linear 48KB cp.async copy of precomputed
// records; all conversion math hoisted to record_kernel. Epilogue writes
// AO pre-rounded to tf32 so the Wo GEMM can consume raw bits.
// ---------------------------------------------------------------------------
#define ATT_DSMEM (49152 + 4*4352)   // 66560

__global__ __launch_bounds__(128) void attn_kernel()
{
    extern __shared__ __align__(16) char dynA[];
    const uint32_t Khi = smem_u32(dynA);
    const uint32_t Klo = Khi + 16384u;
    const uint32_t Vsm = Khi + 32768u;

    const int tid  = threadIdx.x;
    const int lane = tid & 31;
    const int w    = tid >> 5;
    const uint32_t Pb = Khi + 49152u + (uint32_t)w * 4352u;
    const int gid = lane >> 2;
    const int tg  = lane & 3;

    const int qt = (SEQ / 64 - 1) - blockIdx.x;   // heavy tiles first
    const int h  = blockIdx.y;
    const int b  = blockIdx.z;
    const int qbase = b * SEQ + qt * 64;
    const size_t tile0 = (size_t)(b * HEADS + h) * (SEQ / 64) * 4096;

    // ---- persistent Q fragments (hi/lo split) ----
    uint32_t qhi[8][4], qlo[8][4];
    {
        const float* qp = g_Q + (size_t)(qbase + w * 16) * DMODEL + h * DH;
        #pragma unroll
        for (int kb = 0; kb < 8; kb++) {
            float v[4];
            v[0] = qp[(size_t)gid       * DMODEL + kb * 8 + tg];
            v[1] = qp[(size_t)(gid + 8) * DMODEL + kb * 8 + tg];
            v[2] = qp[(size_t)gid       * DMODEL + kb * 8 + tg + 4];
            v[3] = qp[(size_t)(gid + 8) * DMODEL + kb * 8 + tg + 4];
            #pragma unroll
            for (int i = 0; i < 4; i++) {
                qhi[kb][i] = f2tf32(v[i]);
                qlo[kb][i] = f2tf32(v[i] - __uint_as_float(qhi[kb][i]));
            }
        }
    }

    float o[8][4];
    #pragma unroll
    for (int nb = 0; nb < 8; nb++)
        #pragma unroll
        for (int c = 0; c < 4; c++) o[nb][c] = 0.f;
    float mst[2] = {-1e30f, -1e30f};
    float lst[2] = {0.f, 0.f};

    for (int kt = 0; kt <= qt; kt++) {
        __syncthreads();   // previous tile's consumers done

        // ---- producer: linear cp.async copy of this tile's records ----
        {
            const size_t tb = tile0 + (size_t)kt * 4096;
            const float* sH = g_KhiR + tb + tid * 32;
            const float* sL = g_KloR + tb + tid * 32;
            const float* sV = g_VR   + tb + tid * 32;
            uint32_t dH = Khi + (uint32_t)(tid * 128);
            uint32_t dL = Klo + (uint32_t)(tid * 128);
            uint32_t dV = Vsm + (uint32_t)(tid * 128);
            #pragma unroll
            for (int i = 0; i < 8; i++) {
                CP16(dH + i * 16, sH + i * 4);
                CP16(dL + i * 16, sL + i * 4);
                CP16(dV + i * 16, sV + i * 4);
            }
            CP_COMMIT();
            CP_WAIT(0);
        }
        __syncthreads();

        // ---- S = Q K^T (3xTF32) ----
        float s[8][4];
        #pragma unroll
        for (int nb = 0; nb < 8; nb++) {
            s[nb][0] = s[nb][1] = s[nb][2] = s[nb][3] = 0.f;
            #pragma unroll
            for (int kb = 0; kb < 8; kb++) {
                const uint32_t off = (uint32_t)((((kb * 8 + nb) * 64) + lane * 2) * 4);
                uint32_t kh[2], kl[2];
                asm volatile("ld.shared.v2.b32 {%0,%1}, [%2];"
                             : "=r"(kh[0]), "=r"(kh[1]) : "r"(Khi + off));
                asm volatile("ld.shared.v2.b32 {%0,%1}, [%2];"
                             : "=r"(kl[0]), "=r"(kl[1]) : "r"(Klo + off));
                mma_tf32(s[nb], qhi[kb], kh);
                mma_tf32(s[nb], qlo[kb], kh);
                mma_tf32(s[nb], qhi[kb], kl);
            }
        }

        // ---- scale + causal mask (diagonal tile only) ----
        const bool diag = (kt == qt);
        #pragma unroll
        for (int nb = 0; nb < 8; nb++)
            #pragma unroll
            for (int c = 0; c < 4; c++) {
                s[nb][c] *= 0.125f;
                if (diag) {
                    int rl = w * 16 + gid + (c >> 1) * 8;
                    int cl = nb * 8 + 2 * tg + (c & 1);
                    if (cl > rl) s[nb][c] = -1e30f;
                }
            }

        // ---- online softmax ----
        #pragma unroll
        for (int rh = 0; rh < 2; rh++) {
            float mx = -1e30f;
            #pragma unroll
            for (int nb = 0; nb < 8; nb++)
                mx = fmaxf(mx, fmaxf(s[nb][rh * 2], s[nb][rh * 2 + 1]));
            mx = fmaxf(mx, __shfl_xor_sync(0xffffffffu, mx, 1));
            mx = fmaxf(mx, __shfl_xor_sync(0xffffffffu, mx, 2));
            float mnew  = fmaxf(mst[rh], mx);
            float alpha = __expf(mst[rh] - mnew);
            mst[rh] = mnew;
            float sum = 0.f;
            #pragma unroll
            for (int nb = 0; nb < 8; nb++) {
                float e0 = __expf(s[nb][rh * 2]     - mnew);
                float e1 = __expf(s[nb][rh * 2 + 1] - mnew);
                s[nb][rh * 2] = e0; s[nb][rh * 2 + 1] = e1;
                sum += e0 + e1;
            }
            sum += __shfl_xor_sync(0xffffffffu, sum, 1);
            sum += __shfl_xor_sync(0xffffffffu, sum, 2);
            lst[rh] = lst[rh] * alpha + sum;
            #pragma unroll
            for (int nb = 0; nb < 8; nb++) {
                o[nb][rh * 2]     *= alpha;
                o[nb][rh * 2 + 1] *= alpha;
            }
        }

        // ---- write P (tf32 bits) to padded per-warp SMEM ----
        #pragma unroll
        for (int nb = 0; nb < 8; nb++) {
            uint32_t p0 = f2tf32(s[nb][0]), p1 = f2tf32(s[nb][1]);
            uint32_t p2 = f2tf32(s[nb][2]), p3 = f2tf32(s[nb][3]);
            uint32_t o0 = Pb + (uint32_t)(((gid)     * 68 + nb * 8 + 2 * tg) * 4);
            uint32_t o1 = Pb + (uint32_t)(((gid + 8) * 68 + nb * 8 + 2 * tg) * 4);
            asm volatile("st.shared.v2.b32 [%0], {%1,%2};"
                         :: "r"(o0), "r"(p0), "r"(p1) : "memory");
            asm volatile("st.shared.v2.b32 [%0], {%1,%2};"
                         :: "r"(o1), "r"(p2), "r"(p3) : "memory");
        }
        __syncwarp();

        // ---- O += P * V ----
        #pragma unroll
        for (int kb = 0; kb < 8; kb++) {
            uint32_t a[4];
            a[0] = lds32(Pb + (uint32_t)(((gid)     * 68 + kb * 8 + tg)     * 4));
            a[1] = lds32(Pb + (uint32_t)(((gid + 8) * 68 + kb * 8 + tg)     * 4));
            a[2] = lds32(Pb + (uint32_t)(((gid)     * 68 + kb * 8 + tg + 4) * 4));
            a[3] = lds32(Pb + (uint32_t)(((gid + 8) * 68 + kb * 8 + tg + 4) * 4));
            #pragma unroll
            for (int nb = 0; nb < 8; nb++) {
                const uint32_t off = (uint32_t)((((kb * 8 + nb) * 64) + lane * 2) * 4);
                uint32_t bf[2];
                asm volatile("ld.shared.v2.b32 {%0,%1}, [%2];"
                             : "=r"(bf[0]), "=r"(bf[1]) : "r"(Vsm + off));
                mma_tf32(o[nb], a, bf);
            }
        }
        __syncwarp();
    }

    // ---- epilogue: normalize, round to tf32 bits, write g_AO ----
    #pragma unroll
    for (int rh = 0; rh < 2; rh++) {
        float inv = 1.f / lst[rh];
        int row = qbase + w * 16 + gid + rh * 8;
        float* dst = g_AO + (size_t)row * DMODEL + h * DH;
        #pragma unroll
        for (int nb = 0; nb < 8; nb++) {
            uint32_t r0 = f2tf32(o[nb][rh * 2] * inv);
            uint32_t r1 = f2tf32(o[nb][rh * 2 + 1] * inv);
            *(float2*)(dst + nb * 8 + 2 * tg) =
                make_float2(__uint_as_float(r0), __uint_as_float(r1));
        }
    }
}

// ---------------------------------------------------------------------------
// kernel_launch
// ---------------------------------------------------------------------------
extern "C" void kernel_launch(void* const* d_in, const int* in_sizes, int n_in,
                              void* d_out, int out_size)
{
    const float* X    = (const float*)d_in[0];
    const float* cosT = (const float*)d_in[1];
    const float* sinT = (const float*)d_in[2];
    const float* Wq   = (const float*)d_in[4];
    const float* Wk   = (const float*)d_in[5];
    const float* Wv   = (const float*)d_in[6];
    const float* Wo   = (const float*)d_in[7];
    float* out = (float*)d_out;

    float *pXr, *pWqr, *pWkr, *pWvr, *pWor;
    cudaGetSymbolAddress((void**)&pXr,  g_Xr);
    cudaGetSymbolAddress((void**)&pWqr, g_Wqr);
    cudaGetSymbolAddress((void**)&pWkr, g_Wkr);
    cudaGetSymbolAddress((void**)&pWvr, g_Wvr);
    cudaGetSymbolAddress((void**)&pWor, g_Wor);

    cudaFuncSetAttribute(qkv_kernel,
                         cudaFuncAttributeMaxDynamicSharedMemorySize, GEMM_DSMEM);
    cudaFuncSetAttribute(tgemm_kernel,
                         cudaFuncAttributeMaxDynamicSharedMemorySize, GEMM_DSMEM);
    cudaFuncSetAttribute(attn_kernel,
                         cudaFuncAttributeMaxDynamicSharedMemorySize, ATT_DSMEM);

    // tf32 pre-rounding of GEMM inputs
    const int XW4 = TROWS * DMODEL / 4;      // 1M float4
    const int W4  = DMODEL * DMODEL / 4;     // 256K float4
    round_kernel<<<(XW4 + 255) / 256, 256>>>((const float4*)X,  (float4*)pXr,  XW4);
    round_kernel<<<(W4  + 255) / 256, 256>>>((const float4*)Wq, (float4*)pWqr, W4);
    round_kernel<<<(W4  + 255) / 256, 256>>>((const float4*)Wk, (float4*)pWkr, W4);
    round_kernel<<<(W4  + 255) / 256, 256>>>((const float4*)Wv, (float4*)pWvr, W4);
    round_kernel<<<(W4  + 255) / 256, 256>>>((const float4*)Wo, (float4*)pWor, W4);

    dim3 qkv_grid(24, TROWS / 128);              // (24, 32)
    qkv_kernel<<<qkv_grid, 256, GEMM_DSMEM>>>();

    int rope_total = TROWS * HEADS * 32;
    rope_kernel<<<(rope_total + 255) / 256, 256>>>(cosT, sinT);

    dim3 rec_grid(SEQ / 64, HEADS, BATCH);       // (32, 16, 2)
    record_kernel<<<rec_grid, 128>>>();

    dim3 attn_grid(SEQ / 64, HEADS, BATCH);      // (32, 16, 2)
    attn_kernel<<<attn_grid, 128, ATT_DSMEM>>>();

    dim3 gemm_grid(DMODEL / 128, TROWS / 128);   // (8, 32)
    tgemm_kernel<<<gemm_grid, 256, GEMM_DSMEM>>>(out);

    (void)in_sizes; (void)n_in; (void)out_size;
}